// round 14
// baseline (speedup 1.0000x reference)
#include <cuda_runtime.h>
#include <cuda_bf16.h>
#include <math.h>
#include <stdint.h>

#define DM 1024
#define TS 2048
#define NB 2
#define NH 16
#define DH 64
#define DF 4096
#define NT (NB*TS)   // 4096 tokens

// ---------------- scratch (static __device__, no allocations) ----------------
__device__ float g_x1  [(size_t)NT*DM];

__device__ __nv_bfloat16 g_lnh [(size_t)NT*DM];
__device__ __nv_bfloat16 g_lnl [(size_t)NT*DM];
__device__ __nv_bfloat16 g_qh  [(size_t)NT*DM], g_ql [(size_t)NT*DM];
__device__ __nv_bfloat16 g_kbh [(size_t)NT*DM], g_kbl[(size_t)NT*DM];
__device__ __nv_bfloat16 g_vbh [(size_t)NT*DM], g_vbl[(size_t)NT*DM];
__device__ __nv_bfloat16 g_ath [(size_t)NT*DM];
__device__ __nv_bfloat16 g_atl [(size_t)NT*DM];
__device__ __nv_bfloat16 g_hh  [(size_t)NT*DM];
__device__ __nv_bfloat16 g_hl  [(size_t)NT*DM];
__device__ __nv_bfloat16 g_fh  [(size_t)NT*DF];
__device__ __nv_bfloat16 g_fl  [(size_t)NT*DF];
__device__ __nv_bfloat16 g_wqh[(size_t)DM*DM], g_wql[(size_t)DM*DM];
__device__ __nv_bfloat16 g_wkh[(size_t)DM*DM], g_wkl[(size_t)DM*DM];
__device__ __nv_bfloat16 g_wvh[(size_t)DM*DM], g_wvl[(size_t)DM*DM];
__device__ __nv_bfloat16 g_woh[(size_t)DM*DM], g_wol[(size_t)DM*DM];
__device__ __nv_bfloat16 g_w1h[(size_t)DF*DM], g_w1l[(size_t)DF*DM];
__device__ __nv_bfloat16 g_w2h[(size_t)DM*DF], g_w2l[(size_t)DM*DF];

// ===================== helpers ==============================================
__device__ __forceinline__ uint32_t smem_to_u32(const void* p) {
    uint32_t a;
    asm("{ .reg .u64 t; cvta.to.shared.u64 t, %1; cvt.u32.u64 %0, t; }" : "=r"(a) : "l"(p));
    return a;
}
#define SMEM_SWIZZLE_128B(byte_offset) ((byte_offset) ^ (((byte_offset) >> 3) & 0x70))

__device__ __forceinline__ uint32_t pack_bf16(float lo, float hi) {
    __nv_bfloat162 p(__float2bfloat16(lo), __float2bfloat16(hi));
    return *(uint32_t*)&p;
}
__device__ __forceinline__ uint32_t cvt_bf16x2(float a, float b) {
    uint32_t r;
    asm("cvt.rn.bf16x2.f32 %0, %1, %2;" : "=r"(r) : "f"(b), "f"(a));
    return r;
}

#define CP_ASYNC16(dst_smem, src_gptr) \
    asm volatile("cp.async.cg.shared.global [%0], [%1], 16;" \
        :: "r"((uint32_t)(dst_smem)), "l"(src_gptr) : "memory")
#define CP_COMMIT() asm volatile("cp.async.commit_group;" ::: "memory")
#define CP_WAIT0()  asm volatile("cp.async.wait_group 0;" ::: "memory")

// ---- sm_80+ baseline tensor-core ops (always available) --------------------
__device__ __forceinline__ void ldsm_x4(uint32_t addr, uint32_t* r) {
    asm volatile("ldmatrix.sync.aligned.m8n8.x4.shared.b16 {%0,%1,%2,%3}, [%4];"
        : "=r"(r[0]), "=r"(r[1]), "=r"(r[2]), "=r"(r[3]) : "r"(addr));
}
__device__ __forceinline__ void ldsm_x2(uint32_t addr, uint32_t* r) {
    asm volatile("ldmatrix.sync.aligned.m8n8.x2.shared.b16 {%0,%1}, [%2];"
        : "=r"(r[0]), "=r"(r[1]) : "r"(addr));
}
__device__ __forceinline__ void ldsm_x4_trans(uint32_t addr, uint32_t* r) {
    asm volatile("ldmatrix.sync.aligned.m8n8.x4.trans.shared.b16 {%0,%1,%2,%3}, [%4];"
        : "=r"(r[0]), "=r"(r[1]), "=r"(r[2]), "=r"(r[3]) : "r"(addr));
}
__device__ __forceinline__ void mma_16816(float* d, const uint32_t* a, const uint32_t* b) {
    asm volatile("mma.sync.aligned.m16n8k16.row.col.f32.bf16.bf16.f32 "
        "{%0,%1,%2,%3}, {%4,%5,%6,%7}, {%8,%9}, {%0,%1,%2,%3};"
        : "+f"(d[0]), "+f"(d[1]), "+f"(d[2]), "+f"(d[3])
        : "r"(a[0]), "r"(a[1]), "r"(a[2]), "r"(a[3]), "r"(b[0]), "r"(b[1]));
}

// ---- tcgen05 path (only compiled when the sm_103a feature set is present) --
#if defined(__CUDA_ARCH_FEAT_SM103_ALL)
#define HAVE_TC5 1
__device__ __forceinline__ uint32_t elect_one_pred() {
    uint32_t pred;
    asm volatile("{\n\t.reg .pred p;\n\telect.sync _|p, 0xFFFFFFFF;\n\tselp.b32 %0, 1, 0, p;\n\t}" : "=r"(pred));
    return pred;
}
#define MBARRIER_INIT(addr, cnt) \
    asm volatile("mbarrier.init.shared.b64 [%0], %1;" :: "r"((uint32_t)(addr)), "r"((uint32_t)(cnt)) : "memory")
#define MBARRIER_INVAL(addr) \
    asm volatile("mbarrier.inval.shared.b64 [%0];" :: "r"((uint32_t)(addr)) : "memory")
#define MBARRIER_WAIT_PARITY(mbar_smem_addr, phase_parity) do { \
    uint32_t _mbar = (uint32_t)(mbar_smem_addr); \
    uint32_t _parity = (uint32_t)(phase_parity); \
    uint32_t _done; \
    asm volatile("{\n\t.reg .pred p;\n\tmbarrier.try_wait.parity.acquire.cta.shared::cta.b64 p, [%1], %2;\n\tselp.b32 %0, 1, 0, p;\n\t}" \
        : "=r"(_done) : "r"(_mbar), "r"(_parity) : "memory"); \
    if (!_done) { \
        asm volatile("{\n\t.reg .pred P1;\n\tWAIT_LOOP_%=:\n\tmbarrier.try_wait.parity.acquire.cta.shared::cta.b64 P1, [%0], %1, 0x989680;\n\t@P1 bra.uni WAIT_DONE_%=;\n\tbra.uni WAIT_LOOP_%=;\n\tWAIT_DONE_%=:\n\t}" \
            :: "r"(_mbar), "r"(_parity) : "memory"); \
    } \
} while(0)
#define TCGEN05_ALLOC(smem_result_addr, nCols) \
    asm volatile("tcgen05.alloc.cta_group::1.sync.aligned.shared::cta.b32 [%0], %1;" \
        :: "r"((uint32_t)(smem_result_addr)), "r"((uint32_t)(nCols)) : "memory")
#define TCGEN05_DEALLOC(tmem_addr, nCols) \
    asm volatile("tcgen05.dealloc.cta_group::1.sync.aligned.b32 %0, %1;" :: "r"(tmem_addr), "r"((uint32_t)(nCols)))
#define TCGEN05_COMMIT(mbar_smem_addr) \
    asm volatile("tcgen05.commit.cta_group::1.mbarrier::arrive::one.shared::cluster.b64 [%0];" \
        :: "r"((uint32_t)(mbar_smem_addr)) : "memory")
#define TCGEN05_WAIT_LD()  asm volatile("tcgen05.wait::ld.sync.aligned;" ::: "memory")
#define TCGEN05_FENCE_AFTER()  asm volatile("tcgen05.fence::after_thread_sync;" ::: "memory")
#define TCGEN05_FENCE_BEFORE() asm volatile("tcgen05.fence::before_thread_sync;" ::: "memory")
#define TCGEN05_LD_32X32B_X32(r, tmem_addr) \
    asm volatile("tcgen05.ld.sync.aligned.32x32b.x32.b32 " \
        "{%0, %1, %2, %3, %4, %5, %6, %7, %8, %9, %10, %11, %12, %13, %14, %15, " \
        " %16, %17, %18, %19, %20, %21, %22, %23, %24, %25, %26, %27, %28, %29, %30, %31}, [%32];" \
        : "=r"((r)[0]),  "=r"((r)[1]),  "=r"((r)[2]),  "=r"((r)[3]), \
          "=r"((r)[4]),  "=r"((r)[5]),  "=r"((r)[6]),  "=r"((r)[7]), \
          "=r"((r)[8]),  "=r"((r)[9]),  "=r"((r)[10]), "=r"((r)[11]), \
          "=r"((r)[12]), "=r"((r)[13]), "=r"((r)[14]), "=r"((r)[15]), \
          "=r"((r)[16]), "=r"((r)[17]), "=r"((r)[18]), "=r"((r)[19]), \
          "=r"((r)[20]), "=r"((r)[21]), "=r"((r)[22]), "=r"((r)[23]), \
          "=r"((r)[24]), "=r"((r)[25]), "=r"((r)[26]), "=r"((r)[27]), \
          "=r"((r)[28]), "=r"((r)[29]), "=r"((r)[30]), "=r"((r)[31]) \
        : "r"(tmem_addr))

static constexpr uint64_t SMEM_DESC_BASE_SW128 =
    (uint64_t(2)  << 61) | (uint64_t(1) << 46) | (uint64_t(64) << 32) | (uint64_t(1) << 16);
#define MAKE_SMEM_DESC(base_addr) (SMEM_DESC_BASE_SW128 | ((uint64_t)((base_addr) >> 4) & 0x3FFF))

// idesc: D=f32, A=BF16, B=BF16, M=128, N=128, K-major both
static constexpr uint32_t IDESC_BF16_128x128 =
    (1u << 4) | (1u << 7) | (1u << 10) | ((128u / 8u) << 17) | ((128u / 16u) << 24);

__device__ __forceinline__ void mma_bf16_ss(uint32_t d, uint64_t a, uint64_t b, uint32_t en) {
    asm volatile(
        "{\n\t.reg .pred p;\n\tsetp.ne.u32 p, %4, 0;\n\t"
        "tcgen05.mma.cta_group::1.kind::f16 [%0], %1, %2, %3, {%5, %5, %5, %5}, p;\n\t}"
        :: "r"(d), "l"(a), "l"(b), "r"(IDESC_BF16_128x128), "r"(en), "r"(0u)
        : "memory");
}
#else
#define HAVE_TC5 0
#endif

// ===================== misc math ============================================
__device__ __forceinline__ float softplus10(float br) {
    float t = 10.f * br;
    float sp = (t > 20.f) ? t : log1pf(expf(t));
    return sp * 0.1f;
}

// ---------------- fused fp32 -> bf16 hi/lo split (6 arrays) ------------------
__global__ __launch_bounds__(256) void split6_kernel(
    const float* __restrict__ s0, const float* __restrict__ s1,
    const float* __restrict__ s2, const float* __restrict__ s3,
    const float* __restrict__ s4, const float* __restrict__ s5,
    __nv_bfloat16* __restrict__ h0, __nv_bfloat16* __restrict__ l0,
    __nv_bfloat16* __restrict__ h1, __nv_bfloat16* __restrict__ l1,
    __nv_bfloat16* __restrict__ h2, __nv_bfloat16* __restrict__ l2,
    __nv_bfloat16* __restrict__ h3, __nv_bfloat16* __restrict__ l3,
    __nv_bfloat16* __restrict__ h4, __nv_bfloat16* __restrict__ l4,
    __nv_bfloat16* __restrict__ h5, __nv_bfloat16* __restrict__ l5)
{
    int seg = blockIdx.y;
    const float* X; __nv_bfloat16 *H, *L; int n4;
    switch (seg) {
        case 0:  X = s0; H = h0; L = l0; n4 = DM * DM / 4; break;
        case 1:  X = s1; H = h1; L = l1; n4 = DM * DM / 4; break;
        case 2:  X = s2; H = h2; L = l2; n4 = DM * DM / 4; break;
        case 3:  X = s3; H = h3; L = l3; n4 = DM * DM / 4; break;
        case 4:  X = s4; H = h4; L = l4; n4 = DF * DM / 4; break;
        default: X = s5; H = h5; L = l5; n4 = DF * DM / 4; break;
    }
    for (int i = blockIdx.x * 256 + threadIdx.x; i < n4; i += gridDim.x * 256) {
        float4 v = ((const float4*)X)[i];
        float h0f = __bfloat162float(__float2bfloat16(v.x));
        float h1f = __bfloat162float(__float2bfloat16(v.y));
        float h2f = __bfloat162float(__float2bfloat16(v.z));
        float h3f = __bfloat162float(__float2bfloat16(v.w));
        uint2 hp = make_uint2(pack_bf16(h0f, h1f), pack_bf16(h2f, h3f));
        uint2 lp = make_uint2(pack_bf16(v.x - h0f, v.y - h1f), pack_bf16(v.z - h2f, v.w - h3f));
        *(uint2*)(H + (size_t)i * 4) = hp;
        *(uint2*)(L + (size_t)i * 4) = lp;
    }
}

// ---------------- algebraic layernorm -> bf16 hi/lo --------------------------
__global__ __launch_bounds__(256) void ln_kernel(
    const float* __restrict__ X, const float* __restrict__ g,
    const float* __restrict__ be, const float* __restrict__ a,
    const float* __restrict__ br,
    __nv_bfloat16* __restrict__ YH, __nv_bfloat16* __restrict__ YL)
{
    int row = blockIdx.x;
    const float* x = X + (size_t)row * DM;
    float v[4]; float sum = 0.f, sq = 0.f;
    #pragma unroll
    for (int i = 0; i < 4; i++) {
        v[i] = x[threadIdx.x + i * 256];
        sum += v[i]; sq += v[i] * v[i];
    }
    #pragma unroll
    for (int o = 16; o > 0; o >>= 1) {
        sum += __shfl_down_sync(0xffffffffu, sum, o);
        sq  += __shfl_down_sync(0xffffffffu, sq,  o);
    }
    __shared__ float s1[8], s2[8];
    int w = threadIdx.x >> 5, lane = threadIdx.x & 31;
    if (lane == 0) { s1[w] = sum; s2[w] = sq; }
    __syncthreads();
    if (threadIdx.x == 0) {
        float A = 0.f, B = 0.f;
        #pragma unroll
        for (int i = 0; i < 8; i++) { A += s1[i]; B += s2[i]; }
        s1[0] = A; s2[0] = B;
    }
    __syncthreads();
    float mean = s1[0] * (1.f / DM);
    float var  = s2[0] * (1.f / DM) - mean * mean;
    float z = var + 1e-5f;
    float p = a[0] + a[1] * z + a[2] * z * z;
    float b0 = softplus10(br[0]), b1 = softplus10(br[1]), b2 = softplus10(br[2]);
    float q = b0 + b1 * z + b2 * z * z;
    float fac = p / q;
    #pragma unroll
    for (int i = 0; i < 4; i++) {
        int c = threadIdx.x + i * 256;
        float y = (v[i] - mean) * fac * g[c] + be[c];
        __nv_bfloat16 h = __float2bfloat16(y);
        __nv_bfloat16 l = __float2bfloat16(y - __bfloat162float(h));
        YH[(size_t)row * DM + c] = h;
        YL[(size_t)row * DM + c] = l;
    }
}

// ===================== tensor-core bf16x3 GEMM (256x256 tiles) ==============
// C[M,N] = epi( A[M,K] @ B[N,K]^T ),  A = Ah+Al, B = Bh+Bl (bf16 splits).
// M-tile = 256, N-tile = 256; 4 TMEM accumulators (512 cols total).
// A single-buffered (register prefetch); B double-buffered via cp.async.
// EPI: 1 = relu(+bias) -> bf16 hi/lo ; 2 = res + clip(rs)*(+bias) -> f32 ;
//      3 = +bias -> bf16 hi/lo
#define KC 64
#define G_SM_TPTR 0
#define G_SM_MBAR 8
#define G_A_BASE 1024                 // Ah 32KB + Al 32KB = 64KB (single buf)
#define G_OFF_AL 32768
#define G_B_BUF(s) (1024 + 65536 + (s) * 65536)   // Bh 32KB + Bl 32KB per buf
#define G_OFF_BL 32768
#define G_SM_TOTAL (1024 + 65536 + 2 * 65536)     // 197632 B -> 1 CTA/SM

template<int EPI>
__device__ __forceinline__ void gemm_body(
    char* smem, uint32_t sb, int tid,
    const __nv_bfloat16* __restrict__ Ahb, const __nv_bfloat16* __restrict__ Alb,
    const __nv_bfloat16* __restrict__ Bhb, const __nv_bfloat16* __restrict__ Blb,
    const float* __restrict__ bias, const float* __restrict__ res,
    const float* __restrict__ rs_ptr,
    float* __restrict__ C, __nv_bfloat16* __restrict__ Chi, __nv_bfloat16* __restrict__ Clo,
    int bm, int bn, int N, int K)
{
    int wid = tid >> 5, lid = tid & 31;
    const int NC = K / KC;

    float scl = 1.f;
    if (EPI == 2) scl = fminf(fmaxf(*rs_ptr, 0.2f), 1.f);

#if HAVE_TC5
    if (wid == 0) TCGEN05_ALLOC(sb + G_SM_TPTR, 512);
    __syncthreads();
    uint32_t tmem;
    asm volatile("ld.shared.b32 %0, [%1];" : "=r"(tmem) : "r"(sb + G_SM_TPTR));
    if (tid == 0) MBARRIER_INIT(sb + G_SM_MBAR, 1);
    __syncthreads();

    // --- A register prefetch (256 rows x 64 bf16, hi+lo = 16 uint4/thread) --
    uint4 pfa[16];
    auto prefetchA = [&](int c) {
        #pragma unroll
        for (int arr = 0; arr < 2; arr++) {
            const __nv_bfloat16* src = arr ? Alb : Ahb;
            #pragma unroll
            for (int i = 0; i < 8; i++) {
                int idx = i * 256 + tid;
                int row = idx >> 3, v16 = idx & 7;
                pfa[arr * 8 + i] = *(const uint4*)(src + (size_t)row * K + c * KC + v16 * 8);
            }
        }
    };
    auto storeA = [&]() {
        #pragma unroll
        for (int arr = 0; arr < 2; arr++) {
            char* tb = smem + G_A_BASE + (arr ? G_OFF_AL : 0);
            #pragma unroll
            for (int i = 0; i < 8; i++) {
                int idx = i * 256 + tid;
                int row = idx >> 3, v16 = idx & 7;
                uint32_t off = SMEM_SWIZZLE_128B((uint32_t)(row * 128 + v16 * 16));
                *(uint4*)(tb + off) = pfa[arr * 8 + i];
            }
        }
    };
    // --- B cp.async (256 rows x 64 bf16, hi+lo) into buffer buf -------------
    auto loadB_async = [&](int c, int buf) {
        uint32_t bb = sb + G_B_BUF(buf);
        #pragma unroll
        for (int arr = 0; arr < 2; arr++) {
            const __nv_bfloat16* src = arr ? Blb : Bhb;
            uint32_t tb = bb + (arr ? G_OFF_BL : 0);
            #pragma unroll
            for (int i = 0; i < 8; i++) {
                int idx = i * 256 + tid;
                int row = idx >> 3, v16 = idx & 7;
                uint32_t off = SMEM_SWIZZLE_128B((uint32_t)(row * 128 + v16 * 16));
                CP_ASYNC16(tb + off, src + (size_t)row * K + c * KC + v16 * 8);
            }
        }
    };

    prefetchA(0); storeA();
    loadB_async(0, 0); CP_COMMIT(); CP_WAIT0();
    TCGEN05_FENCE_BEFORE();
    __syncthreads();

    for (int c = 0; c < NC; c++) {
        int s = c & 1;
        if (wid == 0) {
            TCGEN05_FENCE_AFTER();
            if (elect_one_pred()) {
                uint64_t dah[2], dal[2], dbh[2], dbl[2];
                dah[0] = MAKE_SMEM_DESC(sb + G_A_BASE);
                dah[1] = MAKE_SMEM_DESC(sb + G_A_BASE + 16384);
                dal[0] = MAKE_SMEM_DESC(sb + G_A_BASE + G_OFF_AL);
                dal[1] = MAKE_SMEM_DESC(sb + G_A_BASE + G_OFF_AL + 16384);
                uint32_t bb = sb + G_B_BUF(s);
                dbh[0] = MAKE_SMEM_DESC(bb);
                dbh[1] = MAKE_SMEM_DESC(bb + 16384);
                dbl[0] = MAKE_SMEM_DESC(bb + G_OFF_BL);
                dbl[1] = MAKE_SMEM_DESC(bb + G_OFF_BL + 16384);
                #pragma unroll
                for (int ks = 0; ks < KC / 16; ks++) {
                    uint32_t en0 = (c == 0 && ks == 0) ? 0u : 1u;
                    #pragma unroll
                    for (int mi = 0; mi < 2; mi++) {
                        #pragma unroll
                        for (int ni = 0; ni < 2; ni++) {
                            uint32_t d = tmem + (mi * 2 + ni) * 128;
                            mma_bf16_ss(d, dah[mi] + ks * 2, dbh[ni] + ks * 2, en0);
                            mma_bf16_ss(d, dah[mi] + ks * 2, dbl[ni] + ks * 2, 1u);
                            mma_bf16_ss(d, dal[mi] + ks * 2, dbh[ni] + ks * 2, 1u);
                        }
                    }
                }
                TCGEN05_COMMIT(sb + G_SM_MBAR);
            }
        }
        // loads for c+1 issued BEFORE the wait: overlap MMA(c).
        // B buffer s^1 safe: its last reader MMA(c-1) was waited last iter.
        if (c + 1 < NC) {
            loadB_async(c + 1, s ^ 1);
            CP_COMMIT();
            prefetchA(c + 1);
        }
        MBARRIER_WAIT_PARITY(sb + G_SM_MBAR, c & 1);   // MMA(c) done -> A free
        CP_WAIT0();
        __syncthreads();
        if (c + 1 < NC) {
            storeA();
            TCGEN05_FENCE_BEFORE();
            __syncthreads();
        }
    }
    TCGEN05_FENCE_AFTER();

    // epilogue: warps 0-3 -> M-half 0, warps 4-7 -> M-half 1; ni = 0,1
    {
        int half = wid >> 2, w4 = wid & 3;
        int m = bm + half * 128 + w4 * 32 + lid;
        #pragma unroll
        for (int ni = 0; ni < 2; ni++) {
            uint32_t tb = tmem + (half * 2 + ni) * 128;
            #pragma unroll
            for (int cb = 0; cb < 4; cb++) {
                uint32_t d[32];
                TCGEN05_LD_32X32B_X32(d, tb + cb * 32);
                TCGEN05_WAIT_LD();
                int n0 = bn + ni * 128 + cb * 32;
                if (EPI == 1 || EPI == 3) {
                    uint32_t hp[16], lp[16];
                    #pragma unroll
                    for (int j2 = 0; j2 < 16; j2++) {
                        float v0 = __uint_as_float(d[j2 * 2])     + __ldg(&bias[n0 + j2 * 2]);
                        float v1 = __uint_as_float(d[j2 * 2 + 1]) + __ldg(&bias[n0 + j2 * 2 + 1]);
                        if (EPI == 1) { v0 = fmaxf(v0, 0.f); v1 = fmaxf(v1, 0.f); }
                        float h0 = __bfloat162float(__float2bfloat16(v0));
                        float h1 = __bfloat162float(__float2bfloat16(v1));
                        hp[j2] = pack_bf16(h0, h1);
                        lp[j2] = pack_bf16(v0 - h0, v1 - h1);
                    }
                    #pragma unroll
                    for (int q = 0; q < 2; q++) {
                        *(uint4*)(Chi + (size_t)m * N + n0 + q * 16)     = *(uint4*)&hp[q * 8];
                        *(uint4*)(Chi + (size_t)m * N + n0 + q * 16 + 8) = *(uint4*)&hp[q * 8 + 4];
                        *(uint4*)(Clo + (size_t)m * N + n0 + q * 16)     = *(uint4*)&lp[q * 8];
                        *(uint4*)(Clo + (size_t)m * N + n0 + q * 16 + 8) = *(uint4*)&lp[q * 8 + 4];
                    }
                } else {
                    #pragma unroll
                    for (int j4 = 0; j4 < 8; j4++) {
                        float o[4];
                        #pragma unroll
                        for (int q = 0; q < 4; q++) {
                            int j = j4 * 4 + q;
                            float v = __uint_as_float(d[j]) + __ldg(&bias[n0 + j]);
                            if (EPI == 2) v = res[(size_t)m * N + n0 + j] + scl * v;
                            o[q] = v;
                        }
                        *(float4*)(C + (size_t)m * N + n0 + j4 * 4) = make_float4(o[0], o[1], o[2], o[3]);
                    }
                }
            }
        }
        TCGEN05_FENCE_BEFORE();
    }
    __syncthreads();
    if (tid == 0) MBARRIER_INVAL(sb + G_SM_MBAR);
    __syncthreads();
    if (wid == 0) TCGEN05_DEALLOC(tmem, 512);
#else
    // ================= mma.sync fallback: 4 x (128x128) sub-GEMMs ==========
    for (int mh = 0; mh < 2; mh++) {
        for (int nh = 0; nh < 2; nh++) {
            const __nv_bfloat16* Ah2 = Ahb + (size_t)mh * 128 * K;
            const __nv_bfloat16* Al2 = Alb + (size_t)mh * 128 * K;
            const __nv_bfloat16* Bh2 = Bhb + (size_t)nh * 128 * K;
            const __nv_bfloat16* Bl2 = Blb + (size_t)nh * 128 * K;
            int bm2 = bm + mh * 128, bn2 = bn + nh * 128;

            auto load_chunk = [&](int c) {
                const __nv_bfloat16* srcs[4] = {Ah2, Al2, Bh2, Bl2};
                #pragma unroll
                for (int arr = 0; arr < 4; arr++) {
                    const __nv_bfloat16* src = srcs[arr];
                    char* tbp = smem + 1024 + arr * 16384;
                    #pragma unroll
                    for (int i = 0; i < 4; i++) {
                        int idx = i * 256 + tid;
                        int row = idx >> 3, v16 = idx & 7;
                        uint4 val = *(const uint4*)(src + (size_t)row * K + c * KC + v16 * 8);
                        uint32_t off = SMEM_SWIZZLE_128B((uint32_t)(row * 128 + v16 * 16));
                        *(uint4*)(tbp + off) = val;
                    }
                }
            };

            int wm = (wid & 3) * 32, wn = (wid >> 2) * 64;
            float acc[2][8][4];
            #pragma unroll
            for (int mi = 0; mi < 2; mi++)
                #pragma unroll
                for (int n = 0; n < 8; n++)
                    #pragma unroll
                    for (int q = 0; q < 4; q++) acc[mi][n][q] = 0.f;

            for (int c = 0; c < NC; c++) {
                load_chunk(c);
                __syncthreads();
                uint32_t tAh = sb + 1024;
                uint32_t tAl = sb + 1024 + 16384;
                uint32_t tBh = sb + 1024 + 32768;
                uint32_t tBl = sb + 1024 + 49152;

                #pragma unroll
                for (int ks = 0; ks < 4; ks++) {
                    int cb = ks * 32;
                    int amat = lid >> 3;
                    int arow = (lid & 7) + ((amat & 1) << 3);
                    int abc  = cb + ((amat >> 1) << 4);
                    uint32_t offA0 = SMEM_SWIZZLE_128B((uint32_t)((wm + arow) * 128 + abc));
                    uint32_t offA1 = SMEM_SWIZZLE_128B((uint32_t)((wm + 16 + arow) * 128 + abc));
                    uint32_t ah0[4], ah1[4], al0[4], al1[4];
                    ldsm_x4(tAh + offA0, ah0);
                    ldsm_x4(tAh + offA1, ah1);
                    ldsm_x4(tAl + offA0, al0);
                    ldsm_x4(tAl + offA1, al1);

                    int bmat = (lid >> 3) & 1;
                    int brow = lid & 7;
                    int bbc  = cb + (bmat << 4);
                    #pragma unroll
                    for (int n = 0; n < 8; n++) {
                        uint32_t offB = SMEM_SWIZZLE_128B((uint32_t)((wn + n * 8 + brow) * 128 + bbc));
                        uint32_t bh[2], bl[2];
                        ldsm_x2(tBh + offB, bh);
                        ldsm_x2(tBl + offB, bl);
                        mma_16816(acc[0][n], ah0, bh);
                        mma_16816(acc[0][n], ah0, bl);
                        mma_16816(acc[0][n], al0, bh);
                        mma_16816(acc[1][n], ah1, bh);
                        mma_16816(acc[1][n], ah1, bl);
                        mma_16816(acc[1][n], al1, bh);
                    }
                }
                __syncthreads();
            }

            #pragma unroll
            for (int mi = 0; mi < 2; mi++) {
                #pragma unroll
                for (int rr = 0; rr < 2; rr++) {
                    int m = bm2 + wm + mi * 16 + (lid >> 2) + rr * 8;
                    #pragma unroll
                    for (int n = 0; n < 8; n++) {
                        int j0 = bn2 + wn + n * 8 + (lid & 3) * 2;
                        float v0 = acc[mi][n][rr * 2 + 0] + __ldg(&bias[j0]);
                        float v1 = acc[mi][n][rr * 2 + 1] + __ldg(&bias[j0 + 1]);
                        if (EPI == 1 || EPI == 3) {
                            if (EPI == 1) { v0 = fmaxf(v0, 0.f); v1 = fmaxf(v1, 0.f); }
                            __nv_bfloat16 h0 = __float2bfloat16(v0);
                            __nv_bfloat16 h1 = __float2bfloat16(v1);
                            Chi[(size_t)m * N + j0]     = h0;
                            Chi[(size_t)m * N + j0 + 1] = h1;
                            Clo[(size_t)m * N + j0]     = __float2bfloat16(v0 - __bfloat162float(h0));
                            Clo[(size_t)m * N + j0 + 1] = __float2bfloat16(v1 - __bfloat162float(h1));
                        } else {
                            if (EPI == 2) {
                                v0 = res[(size_t)m * N + j0]     + scl * v0;
                                v1 = res[(size_t)m * N + j0 + 1] + scl * v1;
                            }
                            *(float2*)(C + (size_t)m * N + j0) = make_float2(v0, v1);
                        }
                    }
                }
            }
            __syncthreads();
        }
    }
#endif
}

template<int EPI>
__global__ __launch_bounds__(256) void gemm_tc(
    const __nv_bfloat16* __restrict__ Ah, const __nv_bfloat16* __restrict__ Al,
    const __nv_bfloat16* __restrict__ Bh, const __nv_bfloat16* __restrict__ Bl,
    const float* __restrict__ bias, const float* __restrict__ res,
    const float* __restrict__ rs_ptr,
    float* __restrict__ C, __nv_bfloat16* __restrict__ Chi, __nv_bfloat16* __restrict__ Clo,
    int M, int N, int K)
{
    extern __shared__ char smem[];
    int bm = blockIdx.y * 256, bn = blockIdx.x * 256;
    gemm_body<EPI>(smem, smem_to_u32(smem), threadIdx.x,
        Ah + (size_t)bm * K, Al + (size_t)bm * K,
        Bh + (size_t)bn * K, Bl + (size_t)bn * K,
        bias, res, rs_ptr, C, Chi, Clo, bm, bn, N, K);
}

// merged QKV: grid.x = 12 (which = bx>>2), grid.y = 16 (256x256 tiles)
__global__ __launch_bounds__(256) void gemm_qkv(
    const __nv_bfloat16* __restrict__ Ah, const __nv_bfloat16* __restrict__ Al,
    const __nv_bfloat16* __restrict__ wqh, const __nv_bfloat16* __restrict__ wql,
    const __nv_bfloat16* __restrict__ wkh, const __nv_bfloat16* __restrict__ wkl,
    const __nv_bfloat16* __restrict__ wvh, const __nv_bfloat16* __restrict__ wvl,
    const float* __restrict__ bq, const float* __restrict__ bk, const float* __restrict__ bv,
    __nv_bfloat16* __restrict__ qh, __nv_bfloat16* __restrict__ ql,
    __nv_bfloat16* __restrict__ kh, __nv_bfloat16* __restrict__ kl,
    __nv_bfloat16* __restrict__ vh, __nv_bfloat16* __restrict__ vl)
{
    extern __shared__ char smem[];
    int which = blockIdx.x >> 2;
    int bn = (blockIdx.x & 3) * 256, bm = blockIdx.y * 256;
    const __nv_bfloat16* Bh = (which == 0) ? wqh : (which == 1) ? wkh : wvh;
    const __nv_bfloat16* Bl = (which == 0) ? wql : (which == 1) ? wkl : wvl;
    const float* bias       = (which == 0) ? bq  : (which == 1) ? bk  : bv;
    __nv_bfloat16* Chi      = (which == 0) ? qh  : (which == 1) ? kh  : vh;
    __nv_bfloat16* Clo      = (which == 0) ? ql  : (which == 1) ? kl  : vl;
    gemm_body<3>(smem, smem_to_u32(smem), threadIdx.x,
        Ah + (size_t)bm * DM, Al + (size_t)bm * DM,
        Bh + (size_t)bn * DM, Bl + (size_t)bn * DM,
        bias, nullptr, nullptr, nullptr, Chi, Clo, bm, bn, DM, DM);
}

// ================ tensor-core causal relu-attention (R13 winner) ============
#define AT_SQH 0
#define AT_SQL 16384
#define AT_KV(s) (32768 + (s) * 32768)
#define AT_SRE 98304
#define AT_TOTAL (98304 + 1024)

__global__ __launch_bounds__(256) void attn_tc_kernel(
    const __nv_bfloat16* __restrict__ Qh, const __nv_bfloat16* __restrict__ Ql,
    const __nv_bfloat16* __restrict__ Kh, const __nv_bfloat16* __restrict__ Kl,
    const __nv_bfloat16* __restrict__ Vh, const __nv_bfloat16* __restrict__ Vl,
    const float* __restrict__ RE,
    __nv_bfloat16* __restrict__ Oh, __nv_bfloat16* __restrict__ Ol)
{
    extern __shared__ char sm[];
    uint32_t sb = smem_to_u32(sm);
    float* sre = (float*)(sm + AT_SRE);
    int tid = threadIdx.x, wid = tid >> 5, lid = tid & 31;
    int qt = (int)gridDim.x - 1 - (int)blockIdx.x;   // heavy tiles first
    int h = blockIdx.y, b = blockIdx.z;
    size_t base = ((size_t)b * TS) * DM + h * DH;
    int Q0 = qt * 128;

    if (tid < 255) sre[tid] = RE[tid * NH + h];

    auto loadKV_async = [&](int kt, int s) {
        uint32_t kb = sb + AT_KV(s);
        #pragma unroll
        for (int i = 0; i < 2; i++) {
            int idx = i * 256 + tid; int r = idx >> 3, c8 = idx & 7;
            size_t g = base + (size_t)(kt * 64 + r) * DM + c8 * 8;
            uint32_t off = SMEM_SWIZZLE_128B((uint32_t)(r * 128 + c8 * 16));
            CP_ASYNC16(kb + 0     + off, Kh + g);
            CP_ASYNC16(kb + 8192  + off, Kl + g);
            CP_ASYNC16(kb + 16384 + off, Vh + g);
            CP_ASYNC16(kb + 24576 + off, Vl + g);
        }
    };

    loadKV_async(0, 0); CP_COMMIT();

    #pragma unroll
    for (int i = 0; i < 4; i++) {
        int idx = i * 256 + tid; int r = idx >> 3, c8 = idx & 7;
        size_t g = base + (size_t)(Q0 + r) * DM + c8 * 8;
        uint32_t off = SMEM_SWIZZLE_128B((uint32_t)(r * 128 + c8 * 16));
        *(uint4*)(sm + AT_SQH + off) = *(const uint4*)(Qh + g);
        *(uint4*)(sm + AT_SQL + off) = *(const uint4*)(Ql + g);
    }
    CP_WAIT0();
    __syncthreads();

    uint32_t qa_h[4][4], qa_l[4][4];
    {
        int amat = lid >> 3;
        int arow = (lid & 7) + ((amat & 1) << 3);
        int acol = (amat >> 1) << 4;
        #pragma unroll
        for (int kk = 0; kk < 4; kk++) {
            uint32_t off = SMEM_SWIZZLE_128B((uint32_t)((wid * 16 + arow) * 128 + kk * 32 + acol));
            ldsm_x4(sb + AT_SQH + off, qa_h[kk]);
            ldsm_x4(sb + AT_SQL + off, qa_l[kk]);
        }
    }

    float acc[8][4];
    #pragma unroll
    for (int dn = 0; dn < 8; dn++)
        #pragma unroll
        for (int q = 0; q < 4; q++) acc[dn][q] = 0.f;
    float rs0 = 0.f, rs1 = 0.f;
    int g4 = lid >> 2, tg = lid & 3;
    int qrow0 = Q0 + wid * 16 + g4;
    int qmax  = Q0 + wid * 16 + 15;
    int wqbase = Q0 + wid * 16;

    int r1 = ((lid >> 4) & 1) * 8 + (lid & 7);
    int c1 = ((lid >> 3) & 1) << 4;
    int r2 = (((lid >> 3) & 1) << 3) + (lid & 7);
    int c2 = ((lid >> 4) & 1) << 4;

    const float c0 = sre[0];
    const int KT = 2 * qt + 2;
    for (int kt = 0; kt < KT; kt++) {
        int s = kt & 1;
        if (kt + 1 < KT) { loadKV_async(kt + 1, s ^ 1); CP_COMMIT(); }

        if (kt * 64 <= qmax) {
            uint32_t kvb = sb + AT_KV(s);
            bool far = (kt * 64 + 63 <= wqbase - 127);

            float sv_[8][4];
            #pragma unroll
            for (int np = 0; np < 4; np++) {
                sv_[2*np][0] = sv_[2*np][1] = sv_[2*np][2] = sv_[2*np][3] = 0.f;
                sv_[2*np+1][0] = sv_[2*np+1][1] = sv_[2*np+1][2] = sv_[2*np+1][3] = 0.f;
                #pragma unroll
                for (int kk = 0; kk < 4; kk++) {
                    uint32_t off = SMEM_SWIZZLE_128B(
                        (uint32_t)((np * 16 + r1) * 128 + kk * 32 + c1));
                    uint32_t rh[4], rl[4];
                    ldsm_x4(kvb + 0    + off, rh);
                    ldsm_x4(kvb + 8192 + off, rl);
                    mma_16816(sv_[2*np],   qa_h[kk], rh);
                    mma_16816(sv_[2*np],   qa_h[kk], rl);
                    mma_16816(sv_[2*np],   qa_l[kk], rh);
                    mma_16816(sv_[2*np+1], qa_h[kk], rh + 2);
                    mma_16816(sv_[2*np+1], qa_h[kk], rl + 2);
                    mma_16816(sv_[2*np+1], qa_l[kk], rh + 2);
                }
            }

            uint32_t wh[4][4], wl[4][4];
            #pragma unroll
            for (int n = 0; n < 8; n++) {
                float wv[4];
                if (far) {
                    #pragma unroll
                    for (int e = 0; e < 4; e++)
                        wv[e] = fmaxf(sv_[n][e] * 0.125f + c0, 0.f) + 1e-6f;
                } else {
                    int kc0 = kt * 64 + n * 8 + tg * 2;
                    #pragma unroll
                    for (int e = 0; e < 4; e++) {
                        int kg = kc0 + (e & 1);
                        int qg = qrow0 + ((e >> 1) << 3);
                        int rel = kg - qg;
                        int rc = (rel < -127 ? -127 : (rel > 127 ? 127 : rel)) + 127;
                        float sv = sv_[n][e] * 0.125f + sre[rc];
                        wv[e] = (kg <= qg) ? (fmaxf(sv, 0.f) + 1e-6f) : 0.f;
                    }
                }
                rs0 += wv[0] + wv[1];
                rs1 += wv[2] + wv[3];
                int kk = n >> 1, a0 = (n & 1) << 1;
                uint32_t hp01 = cvt_bf16x2(wv[0], wv[1]);
                uint32_t hp23 = cvt_bf16x2(wv[2], wv[3]);
                float h0 = __uint_as_float(hp01 << 16);
                float h1 = __uint_as_float(hp01 & 0xffff0000u);
                float h2 = __uint_as_float(hp23 << 16);
                float h3 = __uint_as_float(hp23 & 0xffff0000u);
                wh[kk][a0 + 0] = hp01;
                wh[kk][a0 + 1] = hp23;
                wl[kk][a0 + 0] = cvt_bf16x2(wv[0] - h0, wv[1] - h1);
                wl[kk][a0 + 1] = cvt_bf16x2(wv[2] - h2, wv[3] - h3);
            }

            #pragma unroll
            for (int kk = 0; kk < 4; kk++) {
                #pragma unroll
                for (int dp = 0; dp < 4; dp++) {
                    uint32_t off = SMEM_SWIZZLE_128B(
                        (uint32_t)((kk * 16 + r2) * 128 + dp * 32 + c2));
                    uint32_t vh4[4], vl4[4];
                    ldsm_x4_trans(kvb + 16384 + off, vh4);
                    ldsm_x4_trans(kvb + 24576 + off, vl4);
                    mma_16816(acc[2*dp],   wh[kk], vh4);
                    mma_16816(acc[2*dp],   wh[kk], vl4);
                    mma_16816(acc[2*dp],   wl[kk], vh4);
                    mma_16816(acc[2*dp+1], wh[kk], vh4 + 2);
                    mma_16816(acc[2*dp+1], wh[kk], vl4 + 2);
                    mma_16816(acc[2*dp+1], wl[kk], vh4 + 2);
                }
            }
        }
        CP_WAIT0();
        __syncthreads();
    }

    rs0 += __shfl_xor_sync(0xffffffffu, rs0, 1);
    rs0 += __shfl_xor_sync(0xffffffffu, rs0, 2);
    rs1 += __shfl_xor_sync(0xffffffffu, rs1, 1);
    rs1 += __shfl_xor_sync(0xffffffffu, rs1, 2);
    float inv0 = 1.f / (rs0 + 1e-6f);
    float inv1 = 1.f / (rs1 + 1e-6f);

    #pragma unroll
    for (int dn = 0; dn < 8; dn++) {
        float v0 = acc[dn][0] * inv0, v1 = acc[dn][1] * inv0;
        float v2 = acc[dn][2] * inv1, v3 = acc[dn][3] * inv1;
        size_t o0 = base + (size_t)qrow0 * DM + dn * 8 + tg * 2;
        size_t o1 = o0 + (size_t)8 * DM;
        uint32_t p01 = cvt_bf16x2(v0, v1);
        uint32_t p23 = cvt_bf16x2(v2, v3);
        float h0 = __uint_as_float(p01 << 16);
        float h1 = __uint_as_float(p01 & 0xffff0000u);
        float h2 = __uint_as_float(p23 << 16);
        float h3 = __uint_as_float(p23 & 0xffff0000u);
        *(uint32_t*)(Oh + o0) = p01;
        *(uint32_t*)(Oh + o1) = p23;
        *(uint32_t*)(Ol + o0) = cvt_bf16x2(v0 - h0, v1 - h1);
        *(uint32_t*)(Ol + o1) = cvt_bf16x2(v2 - h2, v3 - h3);
    }
}

// ---------------- driver ----------------------------------------------------
extern "C" void kernel_launch(void* const* d_in, const int* in_sizes, int n_in,
                              void* d_out, int out_size)
{
    const float* x   = (const float*)d_in[0];
    const float* Wq  = (const float*)d_in[2];
    const float* bq  = (const float*)d_in[3];
    const float* Wk  = (const float*)d_in[4];
    const float* bk  = (const float*)d_in[5];
    const float* Wv  = (const float*)d_in[6];
    const float* bv  = (const float*)d_in[7];
    const float* Wo  = (const float*)d_in[8];
    const float* bo  = (const float*)d_in[9];
    const float* re  = (const float*)d_in[10];
    const float* g1  = (const float*)d_in[11];
    const float* be1 = (const float*)d_in[12];
    const float* a1  = (const float*)d_in[13];
    const float* br1 = (const float*)d_in[14];
    const float* g2  = (const float*)d_in[15];
    const float* be2 = (const float*)d_in[16];
    const float* a2  = (const float*)d_in[17];
    const float* br2 = (const float*)d_in[18];
    const float* W1  = (const float*)d_in[19];
    const float* b1  = (const float*)d_in[20];
    const float* W2  = (const float*)d_in[21];
    const float* b2  = (const float*)d_in[22];
    const float* rs  = (const float*)d_in[23];
    float* out = (float*)d_out;

    float *px1;
    cudaGetSymbolAddress((void**)&px1,  g_x1);
    __nv_bfloat16 *lnh,*lnl,*qh,*ql,*kbh,*kbl,*vbh,*vbl,*ath,*atl,*hh,*hl,*fh,*fl;
    __nv_bfloat16 *wqh,*wql,*wkh,*wkl,*wvh,*wvl,*woh,*wol,*w1h,*w1l,*w2h,*w2l;
    cudaGetSymbolAddress((void**)&lnh, g_lnh); cudaGetSymbolAddress((void**)&lnl, g_lnl);
    cudaGetSymbolAddress((void**)&qh,  g_qh ); cudaGetSymbolAddress((void**)&ql,  g_ql );
    cudaGetSymbolAddress((void**)&kbh, g_kbh); cudaGetSymbolAddress((void**)&kbl, g_kbl);
    cudaGetSymbolAddress((void**)&vbh, g_vbh); cudaGetSymbolAddress((void**)&vbl, g_vbl);
    cudaGetSymbolAddress((void**)&ath, g_ath); cudaGetSymbolAddress((void**)&atl, g_atl);
    cudaGetSymbolAddress((void**)&hh,  g_hh ); cudaGetSymbolAddress((void**)&hl,  g_hl );
    cudaGetSymbolAddress((void**)&fh,  g_fh ); cudaGetSymbolAddress((void**)&fl,  g_fl );
    cudaGetSymbolAddress((void**)&wqh, g_wqh); cudaGetSymbolAddress((void**)&wql, g_wql);
    cudaGetSymbolAddress((void**)&wkh, g_wkh); cudaGetSymbolAddress((void**)&wkl, g_wkl);
    cudaGetSymbolAddress((void**)&wvh, g_wvh); cudaGetSymbolAddress((void**)&wvl, g_wvl);
    cudaGetSymbolAddress((void**)&woh, g_woh); cudaGetSymbolAddress((void**)&wol, g_wol);
    cudaGetSymbolAddress((void**)&w1h, g_w1h); cudaGetSymbolAddress((void**)&w1l, g_w1l);
    cudaGetSymbolAddress((void**)&w2h, g_w2h); cudaGetSymbolAddress((void**)&w2l, g_w2l);

    cudaFuncSetAttribute(gemm_tc<1>, cudaFuncAttributeMaxDynamicSharedMemorySize, G_SM_TOTAL);
    cudaFuncSetAttribute(gemm_tc<2>, cudaFuncAttributeMaxDynamicSharedMemorySize, G_SM_TOTAL);
    cudaFuncSetAttribute(gemm_qkv,   cudaFuncAttributeMaxDynamicSharedMemorySize, G_SM_TOTAL);
    cudaFuncSetAttribute(attn_tc_kernel, cudaFuncAttributeMaxDynamicSharedMemorySize, AT_TOTAL);

    // 0: all weight splits fused
    split6_kernel<<<dim3(1024, 6), 256>>>(
        Wq, Wk, Wv, Wo, W1, W2,
        wqh, wql, wkh, wkl, wvh, wvl, woh, wol, w1h, w1l, w2h, w2l);

    // 1: ln1 -> bf16 hi/lo
    ln_kernel<<<NT, 256>>>(x, g1, be1, a1, br1, lnh, lnl);

    // 2: merged QKV projections (256x256 tiles) -> bf16 hi/lo
    gemm_qkv<<<dim3(12, NT / 256), 256, G_SM_TOTAL>>>(
        lnh, lnl, wqh, wql, wkh, wkl, wvh, wvl,
        bq, bk, bv, qh, ql, kbh, kbl, vbh, vbl);

    // 3: attention -> bf16 hi/lo
    attn_tc_kernel<<<dim3(TS / 128, NH, NB), 256, AT_TOTAL>>>(
        qh, ql, kbh, kbl, vbh, vbl, re, ath, atl);

    // 4: O projection + residual
    gemm_tc<2><<<dim3(DM / 256, NT / 256), 256, G_SM_TOTAL>>>(
        ath, atl, woh, wol, bo, x, rs, px1, nullptr, nullptr, NT, DM, DM);

    // 5: ln2 -> bf16 hi/lo
    ln_kernel<<<NT, 256>>>(px1, g2, be2, a2, br2, hh, hl);

    // 6: FFN1 (relu) -> bf16 hi/lo
    gemm_tc<1><<<dim3(DF / 256, NT / 256), 256, G_SM_TOTAL>>>(
        hh, hl, w1h, w1l, b1, nullptr, nullptr, nullptr, fh, fl, NT, DF, DM);

    // 7: FFN2 + residual -> out
    gemm_tc<2><<<dim3(DM / 256, NT / 256), 256, G_SM_TOTAL>>>(
        fh, fl, w2h, w2l, b2, px1, rs, out, nullptr, nullptr, NT, DM, DF);
}

// round 15
// speedup vs baseline: 1.2189x; 1.2189x over previous
#include <cuda_runtime.h>
#include <cuda_bf16.h>
#include <math.h>
#include <stdint.h>

#define DM 1024
#define TS 2048
#define NB 2
#define NH 16
#define DH 64
#define DF 4096
#define NT (NB*TS)   // 4096 tokens

// ---------------- scratch (static __device__, no allocations) ----------------
__device__ float g_x1  [(size_t)NT*DM];

__device__ __nv_bfloat16 g_lnh [(size_t)NT*DM];
__device__ __nv_bfloat16 g_lnl [(size_t)NT*DM];
__device__ __nv_bfloat16 g_qh  [(size_t)NT*DM], g_ql [(size_t)NT*DM];
__device__ __nv_bfloat16 g_kbh [(size_t)NT*DM], g_kbl[(size_t)NT*DM];
__device__ __nv_bfloat16 g_vbh [(size_t)NT*DM], g_vbl[(size_t)NT*DM];
__device__ __nv_bfloat16 g_ath [(size_t)NT*DM];
__device__ __nv_bfloat16 g_atl [(size_t)NT*DM];
__device__ __nv_bfloat16 g_hh  [(size_t)NT*DM];
__device__ __nv_bfloat16 g_hl  [(size_t)NT*DM];
__device__ __nv_bfloat16 g_fh  [(size_t)NT*DF];
__device__ __nv_bfloat16 g_fl  [(size_t)NT*DF];
__device__ __nv_bfloat16 g_wqh[(size_t)DM*DM], g_wql[(size_t)DM*DM];
__device__ __nv_bfloat16 g_wkh[(size_t)DM*DM], g_wkl[(size_t)DM*DM];
__device__ __nv_bfloat16 g_wvh[(size_t)DM*DM], g_wvl[(size_t)DM*DM];
__device__ __nv_bfloat16 g_woh[(size_t)DM*DM], g_wol[(size_t)DM*DM];
__device__ __nv_bfloat16 g_w1h[(size_t)DF*DM], g_w1l[(size_t)DF*DM];
__device__ __nv_bfloat16 g_w2h[(size_t)DM*DF], g_w2l[(size_t)DM*DF];

// ===================== helpers ==============================================
__device__ __forceinline__ uint32_t smem_to_u32(const void* p) {
    uint32_t a;
    asm("{ .reg .u64 t; cvta.to.shared.u64 t, %1; cvt.u32.u64 %0, t; }" : "=r"(a) : "l"(p));
    return a;
}
#define SMEM_SWIZZLE_128B(byte_offset) ((byte_offset) ^ (((byte_offset) >> 3) & 0x70))

__device__ __forceinline__ uint32_t pack_bf16(float lo, float hi) {
    __nv_bfloat162 p(__float2bfloat16(lo), __float2bfloat16(hi));
    return *(uint32_t*)&p;
}
// pack pair with single cvt (identical RN rounding): low = a, high = b
__device__ __forceinline__ uint32_t cvt_bf16x2(float a, float b) {
    uint32_t r;
    asm("cvt.rn.bf16x2.f32 %0, %1, %2;" : "=r"(r) : "f"(b), "f"(a));
    return r;
}

#define CP_ASYNC16(dst_smem, src_gptr) \
    asm volatile("cp.async.cg.shared.global [%0], [%1], 16;" \
        :: "r"((uint32_t)(dst_smem)), "l"(src_gptr) : "memory")
#define CP_COMMIT() asm volatile("cp.async.commit_group;" ::: "memory")
#define CP_WAIT0()  asm volatile("cp.async.wait_group 0;" ::: "memory")

// ---- sm_80+ baseline tensor-core ops (always available) --------------------
__device__ __forceinline__ void ldsm_x4(uint32_t addr, uint32_t* r) {
    asm volatile("ldmatrix.sync.aligned.m8n8.x4.shared.b16 {%0,%1,%2,%3}, [%4];"
        : "=r"(r[0]), "=r"(r[1]), "=r"(r[2]), "=r"(r[3]) : "r"(addr));
}
__device__ __forceinline__ void ldsm_x2(uint32_t addr, uint32_t* r) {
    asm volatile("ldmatrix.sync.aligned.m8n8.x2.shared.b16 {%0,%1}, [%2];"
        : "=r"(r[0]), "=r"(r[1]) : "r"(addr));
}
__device__ __forceinline__ void ldsm_x4_trans(uint32_t addr, uint32_t* r) {
    asm volatile("ldmatrix.sync.aligned.m8n8.x4.trans.shared.b16 {%0,%1,%2,%3}, [%4];"
        : "=r"(r[0]), "=r"(r[1]), "=r"(r[2]), "=r"(r[3]) : "r"(addr));
}
__device__ __forceinline__ void mma_16816(float* d, const uint32_t* a, const uint32_t* b) {
    asm volatile("mma.sync.aligned.m16n8k16.row.col.f32.bf16.bf16.f32 "
        "{%0,%1,%2,%3}, {%4,%5,%6,%7}, {%8,%9}, {%0,%1,%2,%3};"
        : "+f"(d[0]), "+f"(d[1]), "+f"(d[2]), "+f"(d[3])
        : "r"(a[0]), "r"(a[1]), "r"(a[2]), "r"(a[3]), "r"(b[0]), "r"(b[1]));
}

// ---- tcgen05 path (only compiled when the sm_103a feature set is present) --
#if defined(__CUDA_ARCH_FEAT_SM103_ALL)
#define HAVE_TC5 1
__device__ __forceinline__ uint32_t elect_one_pred() {
    uint32_t pred;
    asm volatile("{\n\t.reg .pred p;\n\telect.sync _|p, 0xFFFFFFFF;\n\tselp.b32 %0, 1, 0, p;\n\t}" : "=r"(pred));
    return pred;
}
#define MBARRIER_INIT(addr, cnt) \
    asm volatile("mbarrier.init.shared.b64 [%0], %1;" :: "r"((uint32_t)(addr)), "r"((uint32_t)(cnt)) : "memory")
#define MBARRIER_INVAL(addr) \
    asm volatile("mbarrier.inval.shared.b64 [%0];" :: "r"((uint32_t)(addr)) : "memory")
#define MBARRIER_WAIT_PARITY(mbar_smem_addr, phase_parity) do { \
    uint32_t _mbar = (uint32_t)(mbar_smem_addr); \
    uint32_t _parity = (uint32_t)(phase_parity); \
    uint32_t _done; \
    asm volatile("{\n\t.reg .pred p;\n\tmbarrier.try_wait.parity.acquire.cta.shared::cta.b64 p, [%1], %2;\n\tselp.b32 %0, 1, 0, p;\n\t}" \
        : "=r"(_done) : "r"(_mbar), "r"(_parity) : "memory"); \
    if (!_done) { \
        asm volatile("{\n\t.reg .pred P1;\n\tWAIT_LOOP_%=:\n\tmbarrier.try_wait.parity.acquire.cta.shared::cta.b64 P1, [%0], %1, 0x989680;\n\t@P1 bra.uni WAIT_DONE_%=;\n\tbra.uni WAIT_LOOP_%=;\n\tWAIT_DONE_%=:\n\t}" \
            :: "r"(_mbar), "r"(_parity) : "memory"); \
    } \
} while(0)
#define TCGEN05_ALLOC(smem_result_addr, nCols) \
    asm volatile("tcgen05.alloc.cta_group::1.sync.aligned.shared::cta.b32 [%0], %1;" \
        :: "r"((uint32_t)(smem_result_addr)), "r"((uint32_t)(nCols)) : "memory")
#define TCGEN05_DEALLOC(tmem_addr, nCols) \
    asm volatile("tcgen05.dealloc.cta_group::1.sync.aligned.b32 %0, %1;" :: "r"(tmem_addr), "r"((uint32_t)(nCols)))
#define TCGEN05_COMMIT(mbar_smem_addr) \
    asm volatile("tcgen05.commit.cta_group::1.mbarrier::arrive::one.shared::cluster.b64 [%0];" \
        :: "r"((uint32_t)(mbar_smem_addr)) : "memory")
#define TCGEN05_WAIT_LD()  asm volatile("tcgen05.wait::ld.sync.aligned;" ::: "memory")
#define TCGEN05_FENCE_AFTER()  asm volatile("tcgen05.fence::after_thread_sync;" ::: "memory")
#define TCGEN05_FENCE_BEFORE() asm volatile("tcgen05.fence::before_thread_sync;" ::: "memory")
#define TCGEN05_LD_32X32B_X32(r, tmem_addr) \
    asm volatile("tcgen05.ld.sync.aligned.32x32b.x32.b32 " \
        "{%0, %1, %2, %3, %4, %5, %6, %7, %8, %9, %10, %11, %12, %13, %14, %15, " \
        " %16, %17, %18, %19, %20, %21, %22, %23, %24, %25, %26, %27, %28, %29, %30, %31}, [%32];" \
        : "=r"((r)[0]),  "=r"((r)[1]),  "=r"((r)[2]),  "=r"((r)[3]), \
          "=r"((r)[4]),  "=r"((r)[5]),  "=r"((r)[6]),  "=r"((r)[7]), \
          "=r"((r)[8]),  "=r"((r)[9]),  "=r"((r)[10]), "=r"((r)[11]), \
          "=r"((r)[12]), "=r"((r)[13]), "=r"((r)[14]), "=r"((r)[15]), \
          "=r"((r)[16]), "=r"((r)[17]), "=r"((r)[18]), "=r"((r)[19]), \
          "=r"((r)[20]), "=r"((r)[21]), "=r"((r)[22]), "=r"((r)[23]), \
          "=r"((r)[24]), "=r"((r)[25]), "=r"((r)[26]), "=r"((r)[27]), \
          "=r"((r)[28]), "=r"((r)[29]), "=r"((r)[30]), "=r"((r)[31]) \
        : "r"(tmem_addr))

static constexpr uint64_t SMEM_DESC_BASE_SW128 =
    (uint64_t(2)  << 61) | (uint64_t(1) << 46) | (uint64_t(64) << 32) | (uint64_t(1) << 16);
#define MAKE_SMEM_DESC(base_addr) (SMEM_DESC_BASE_SW128 | ((uint64_t)((base_addr) >> 4) & 0x3FFF))

// idesc: D=f32, A=BF16, B=BF16, M=128, N=128, K-major both
static constexpr uint32_t IDESC_BF16_128x128 =
    (1u << 4) | (1u << 7) | (1u << 10) | ((128u / 8u) << 17) | ((128u / 16u) << 24);

__device__ __forceinline__ void mma_bf16_ss(uint32_t d, uint64_t a, uint64_t b, uint32_t en) {
    asm volatile(
        "{\n\t.reg .pred p;\n\tsetp.ne.u32 p, %4, 0;\n\t"
        "tcgen05.mma.cta_group::1.kind::f16 [%0], %1, %2, %3, {%5, %5, %5, %5}, p;\n\t}"
        :: "r"(d), "l"(a), "l"(b), "r"(IDESC_BF16_128x128), "r"(en), "r"(0u)
        : "memory");
}
#else
#define HAVE_TC5 0
#endif

// ===================== misc math ============================================
__device__ __forceinline__ float softplus10(float br) {
    float t = 10.f * br;
    float sp = (t > 20.f) ? t : log1pf(expf(t));
    return sp * 0.1f;
}

// ---------------- fused fp32 -> bf16 hi/lo split (6 arrays) ------------------
__global__ __launch_bounds__(256) void split6_kernel(
    const float* __restrict__ s0, const float* __restrict__ s1,
    const float* __restrict__ s2, const float* __restrict__ s3,
    const float* __restrict__ s4, const float* __restrict__ s5,
    __nv_bfloat16* __restrict__ h0, __nv_bfloat16* __restrict__ l0,
    __nv_bfloat16* __restrict__ h1, __nv_bfloat16* __restrict__ l1,
    __nv_bfloat16* __restrict__ h2, __nv_bfloat16* __restrict__ l2,
    __nv_bfloat16* __restrict__ h3, __nv_bfloat16* __restrict__ l3,
    __nv_bfloat16* __restrict__ h4, __nv_bfloat16* __restrict__ l4,
    __nv_bfloat16* __restrict__ h5, __nv_bfloat16* __restrict__ l5)
{
    int seg = blockIdx.y;
    const float* X; __nv_bfloat16 *H, *L; int n4;
    switch (seg) {
        case 0:  X = s0; H = h0; L = l0; n4 = DM * DM / 4; break;
        case 1:  X = s1; H = h1; L = l1; n4 = DM * DM / 4; break;
        case 2:  X = s2; H = h2; L = l2; n4 = DM * DM / 4; break;
        case 3:  X = s3; H = h3; L = l3; n4 = DM * DM / 4; break;
        case 4:  X = s4; H = h4; L = l4; n4 = DF * DM / 4; break;
        default: X = s5; H = h5; L = l5; n4 = DF * DM / 4; break;
    }
    for (int i = blockIdx.x * 256 + threadIdx.x; i < n4; i += gridDim.x * 256) {
        float4 v = ((const float4*)X)[i];
        float h0f = __bfloat162float(__float2bfloat16(v.x));
        float h1f = __bfloat162float(__float2bfloat16(v.y));
        float h2f = __bfloat162float(__float2bfloat16(v.z));
        float h3f = __bfloat162float(__float2bfloat16(v.w));
        uint2 hp = make_uint2(pack_bf16(h0f, h1f), pack_bf16(h2f, h3f));
        uint2 lp = make_uint2(pack_bf16(v.x - h0f, v.y - h1f), pack_bf16(v.z - h2f, v.w - h3f));
        *(uint2*)(H + (size_t)i * 4) = hp;
        *(uint2*)(L + (size_t)i * 4) = lp;
    }
}

// ---------------- algebraic layernorm -> bf16 hi/lo --------------------------
__global__ __launch_bounds__(256) void ln_kernel(
    const float* __restrict__ X, const float* __restrict__ g,
    const float* __restrict__ be, const float* __restrict__ a,
    const float* __restrict__ br,
    __nv_bfloat16* __restrict__ YH, __nv_bfloat16* __restrict__ YL)
{
    int row = blockIdx.x;
    const float* x = X + (size_t)row * DM;
    float v[4]; float sum = 0.f, sq = 0.f;
    #pragma unroll
    for (int i = 0; i < 4; i++) {
        v[i] = x[threadIdx.x + i * 256];
        sum += v[i]; sq += v[i] * v[i];
    }
    #pragma unroll
    for (int o = 16; o > 0; o >>= 1) {
        sum += __shfl_down_sync(0xffffffffu, sum, o);
        sq  += __shfl_down_sync(0xffffffffu, sq,  o);
    }
    __shared__ float s1[8], s2[8];
    int w = threadIdx.x >> 5, lane = threadIdx.x & 31;
    if (lane == 0) { s1[w] = sum; s2[w] = sq; }
    __syncthreads();
    if (threadIdx.x == 0) {
        float A = 0.f, B = 0.f;
        #pragma unroll
        for (int i = 0; i < 8; i++) { A += s1[i]; B += s2[i]; }
        s1[0] = A; s2[0] = B;
    }
    __syncthreads();
    float mean = s1[0] * (1.f / DM);
    float var  = s2[0] * (1.f / DM) - mean * mean;
    float z = var + 1e-5f;
    float p = a[0] + a[1] * z + a[2] * z * z;
    float b0 = softplus10(br[0]), b1 = softplus10(br[1]), b2 = softplus10(br[2]);
    float q = b0 + b1 * z + b2 * z * z;
    float fac = p / q;
    #pragma unroll
    for (int i = 0; i < 4; i++) {
        int c = threadIdx.x + i * 256;
        float y = (v[i] - mean) * fac * g[c] + be[c];
        __nv_bfloat16 h = __float2bfloat16(y);
        __nv_bfloat16 l = __float2bfloat16(y - __bfloat162float(h));
        YH[(size_t)row * DM + c] = h;
        YL[(size_t)row * DM + c] = l;
    }
}

// ===================== tensor-core bf16x3 GEMM (256x128 tiles) ==============
// C[M,N] = epi( A[M,K] @ B[N,K]^T ),  A = Ah+Al, B = Bh+Bl (bf16 splits).
// M-tile = 256 (two 128-row halves share one B tile; two TMEM accumulators).
// EPI: 1 = relu(+bias) -> bf16 hi/lo ; 2 = res + clip(rs)*(+bias) -> f32 ;
//      3 = +bias -> bf16 hi/lo
// Pipelined: commit MMA(c), wait MMA(c-1), cp.async chunk c+1 into freed buf.
#define KC 64
#define G_SM_TPTR 0
#define G_SM_MBAR 8
#define G_BUF_STRIDE 98304               // 96KB per buffer
#define G_OFF_AH 0
#define G_OFF_AL 32768
#define G_OFF_BH 65536
#define G_OFF_BL 81920
#define G_SM_BUF(buf) (1024 + (buf) * G_BUF_STRIDE)
#define G_SM_TOTAL (1024 + 2 * G_BUF_STRIDE)   // 197632 B -> 1 CTA/SM

template<int EPI>
__device__ __forceinline__ void gemm_body(
    char* smem, uint32_t sb, int tid,
    const __nv_bfloat16* __restrict__ Ahb, const __nv_bfloat16* __restrict__ Alb,
    const __nv_bfloat16* __restrict__ Bhb, const __nv_bfloat16* __restrict__ Blb,
    const float* __restrict__ bias, const float* __restrict__ res,
    const float* __restrict__ rs_ptr,
    float* __restrict__ C, __nv_bfloat16* __restrict__ Chi, __nv_bfloat16* __restrict__ Clo,
    int bm, int bn, int N, int K)
{
    int wid = tid >> 5, lid = tid & 31;
    const int NC = K / KC;

    float scl = 1.f;
    if (EPI == 2) scl = fminf(fmaxf(*rs_ptr, 0.2f), 1.f);

#if HAVE_TC5
    if (wid == 0) TCGEN05_ALLOC(sb + G_SM_TPTR, 256);
    __syncthreads();
    uint32_t tmem;
    asm volatile("ld.shared.b32 %0, [%1];" : "=r"(tmem) : "r"(sb + G_SM_TPTR));
    if (tid == 0) MBARRIER_INIT(sb + G_SM_MBAR, 1);
    __syncthreads();

    auto loadAB_async = [&](int c, int buf) {
        uint32_t bb = sb + G_SM_BUF(buf);
        #pragma unroll
        for (int arr = 0; arr < 2; arr++) {
            const __nv_bfloat16* src = arr ? Alb : Ahb;
            uint32_t tb = bb + (arr ? G_OFF_AL : G_OFF_AH);
            #pragma unroll
            for (int i = 0; i < 8; i++) {
                int idx = i * 256 + tid;
                int row = idx >> 3, v16 = idx & 7;
                uint32_t off = SMEM_SWIZZLE_128B((uint32_t)(row * 128 + v16 * 16));
                CP_ASYNC16(tb + off, src + (size_t)row * K + c * KC + v16 * 8);
            }
        }
        #pragma unroll
        for (int arr = 0; arr < 2; arr++) {
            const __nv_bfloat16* src = arr ? Blb : Bhb;
            uint32_t tb = bb + (arr ? G_OFF_BL : G_OFF_BH);
            #pragma unroll
            for (int i = 0; i < 4; i++) {
                int idx = i * 256 + tid;
                int row = idx >> 3, v16 = idx & 7;
                uint32_t off = SMEM_SWIZZLE_128B((uint32_t)(row * 128 + v16 * 16));
                CP_ASYNC16(tb + off, src + (size_t)row * K + c * KC + v16 * 8);
            }
        }
    };

    loadAB_async(0, 0); CP_COMMIT(); CP_WAIT0();
    TCGEN05_FENCE_BEFORE();
    __syncthreads();

    for (int c = 0; c < NC; c++) {
        int s = c & 1;
        if (wid == 0) {
            TCGEN05_FENCE_AFTER();
            if (elect_one_pred()) {
                uint32_t bb = sb + G_SM_BUF(s);
                uint64_t dah0 = MAKE_SMEM_DESC(bb + G_OFF_AH);
                uint64_t dah1 = MAKE_SMEM_DESC(bb + G_OFF_AH + 16384);
                uint64_t dal0 = MAKE_SMEM_DESC(bb + G_OFF_AL);
                uint64_t dal1 = MAKE_SMEM_DESC(bb + G_OFF_AL + 16384);
                uint64_t dbh  = MAKE_SMEM_DESC(bb + G_OFF_BH);
                uint64_t dbl  = MAKE_SMEM_DESC(bb + G_OFF_BL);
                #pragma unroll
                for (int ks = 0; ks < KC / 16; ks++) {
                    uint32_t en0 = (c == 0 && ks == 0) ? 0u : 1u;
                    mma_bf16_ss(tmem,       dah0 + ks * 2, dbh + ks * 2, en0);
                    mma_bf16_ss(tmem,       dah0 + ks * 2, dbl + ks * 2, 1u);
                    mma_bf16_ss(tmem,       dal0 + ks * 2, dbh + ks * 2, 1u);
                    mma_bf16_ss(tmem + 128, dah1 + ks * 2, dbh + ks * 2, en0);
                    mma_bf16_ss(tmem + 128, dah1 + ks * 2, dbl + ks * 2, 1u);
                    mma_bf16_ss(tmem + 128, dal1 + ks * 2, dbh + ks * 2, 1u);
                }
                TCGEN05_COMMIT(sb + G_SM_MBAR);
            }
        }
        // wait only for MMA(c-1); MMA(c) keeps running during the load below
        if (c >= 1) MBARRIER_WAIT_PARITY(sb + G_SM_MBAR, (c - 1) & 1);
        if (c + 1 < NC) {
            loadAB_async(c + 1, s ^ 1);
            CP_COMMIT(); CP_WAIT0();
            TCGEN05_FENCE_BEFORE();
        }
        __syncthreads();
    }
    MBARRIER_WAIT_PARITY(sb + G_SM_MBAR, (NC - 1) & 1);
    TCGEN05_FENCE_AFTER();

    // epilogue: all 8 warps; warps 0-3 -> accumulator 0 (rows 0-127),
    // warps 4-7 -> accumulator 1 at tmem+128 (rows 128-255); lanes (wid&3)*32
    {
        int half = wid >> 2, w4 = wid & 3;
        int m = bm + half * 128 + w4 * 32 + lid;
        uint32_t tb = tmem + half * 128;
        #pragma unroll
        for (int cb = 0; cb < 4; cb++) {
            uint32_t d[32];
            TCGEN05_LD_32X32B_X32(d, tb + cb * 32);
            TCGEN05_WAIT_LD();
            int n0 = bn + cb * 32;
            if (EPI == 1 || EPI == 3) {
                uint32_t hp[16], lp[16];
                #pragma unroll
                for (int j2 = 0; j2 < 16; j2++) {
                    float v0 = __uint_as_float(d[j2 * 2])     + __ldg(&bias[n0 + j2 * 2]);
                    float v1 = __uint_as_float(d[j2 * 2 + 1]) + __ldg(&bias[n0 + j2 * 2 + 1]);
                    if (EPI == 1) { v0 = fmaxf(v0, 0.f); v1 = fmaxf(v1, 0.f); }
                    float h0 = __bfloat162float(__float2bfloat16(v0));
                    float h1 = __bfloat162float(__float2bfloat16(v1));
                    hp[j2] = pack_bf16(h0, h1);
                    lp[j2] = pack_bf16(v0 - h0, v1 - h1);
                }
                #pragma unroll
                for (int q = 0; q < 2; q++) {
                    *(uint4*)(Chi + (size_t)m * N + n0 + q * 16)     = *(uint4*)&hp[q * 8];
                    *(uint4*)(Chi + (size_t)m * N + n0 + q * 16 + 8) = *(uint4*)&hp[q * 8 + 4];
                    *(uint4*)(Clo + (size_t)m * N + n0 + q * 16)     = *(uint4*)&lp[q * 8];
                    *(uint4*)(Clo + (size_t)m * N + n0 + q * 16 + 8) = *(uint4*)&lp[q * 8 + 4];
                }
            } else {
                #pragma unroll
                for (int j4 = 0; j4 < 8; j4++) {
                    float o[4];
                    #pragma unroll
                    for (int q = 0; q < 4; q++) {
                        int j = j4 * 4 + q;
                        float v = __uint_as_float(d[j]) + __ldg(&bias[n0 + j]);
                        if (EPI == 2) v = res[(size_t)m * N + n0 + j] + scl * v;
                        o[q] = v;
                    }
                    *(float4*)(C + (size_t)m * N + n0 + j4 * 4) = make_float4(o[0], o[1], o[2], o[3]);
                }
            }
        }
        TCGEN05_FENCE_BEFORE();
    }
    __syncthreads();
    if (tid == 0) MBARRIER_INVAL(sb + G_SM_MBAR);
    __syncthreads();
    if (wid == 0) TCGEN05_DEALLOC(tmem, 256);
#else
    // ======================= mma.sync fallback path (two 128-row halves) ====
    for (int mh = 0; mh < 2; mh++) {
        const __nv_bfloat16* Ah2 = Ahb + (size_t)mh * 128 * K;
        const __nv_bfloat16* Al2 = Alb + (size_t)mh * 128 * K;
        int bm2 = bm + mh * 128;

        auto load_chunk = [&](int c) {
            const __nv_bfloat16* srcs[4] = {Ah2, Al2, Bhb, Blb};
            uint32_t offs[4] = {G_OFF_AH, G_OFF_AL, G_OFF_BH, G_OFF_BL};
            #pragma unroll
            for (int arr = 0; arr < 4; arr++) {
                const __nv_bfloat16* src = srcs[arr];
                char* tbp = smem + 1024 + offs[arr];
                #pragma unroll
                for (int i = 0; i < 4; i++) {
                    int idx = i * 256 + tid;
                    int row = idx >> 3, v16 = idx & 7;
                    uint4 val = *(const uint4*)(src + (size_t)row * K + c * KC + v16 * 8);
                    uint32_t off = SMEM_SWIZZLE_128B((uint32_t)(row * 128 + v16 * 16));
                    *(uint4*)(tbp + off) = val;
                }
            }
        };

        int wm = (wid & 3) * 32, wn = (wid >> 2) * 64;
        float acc[2][8][4];
        #pragma unroll
        for (int mi = 0; mi < 2; mi++)
            #pragma unroll
            for (int n = 0; n < 8; n++)
                #pragma unroll
                for (int q = 0; q < 4; q++) acc[mi][n][q] = 0.f;

        for (int c = 0; c < NC; c++) {
            load_chunk(c);
            __syncthreads();
            uint32_t tAh = sb + 1024 + G_OFF_AH;
            uint32_t tAl = sb + 1024 + G_OFF_AL;
            uint32_t tBh = sb + 1024 + G_OFF_BH;
            uint32_t tBl = sb + 1024 + G_OFF_BL;

            #pragma unroll
            for (int ks = 0; ks < 4; ks++) {
                int cb = ks * 32;
                int amat = lid >> 3;
                int arow = (lid & 7) + ((amat & 1) << 3);
                int abc  = cb + ((amat >> 1) << 4);
                uint32_t offA0 = SMEM_SWIZZLE_128B((uint32_t)((wm + arow) * 128 + abc));
                uint32_t offA1 = SMEM_SWIZZLE_128B((uint32_t)((wm + 16 + arow) * 128 + abc));
                uint32_t ah0[4], ah1[4], al0[4], al1[4];
                ldsm_x4(tAh + offA0, ah0);
                ldsm_x4(tAh + offA1, ah1);
                ldsm_x4(tAl + offA0, al0);
                ldsm_x4(tAl + offA1, al1);

                int bmat = (lid >> 3) & 1;
                int brow = lid & 7;
                int bbc  = cb + (bmat << 4);
                #pragma unroll
                for (int n = 0; n < 8; n++) {
                    uint32_t offB = SMEM_SWIZZLE_128B((uint32_t)((wn + n * 8 + brow) * 128 + bbc));
                    uint32_t bh[2], bl[2];
                    ldsm_x2(tBh + offB, bh);
                    ldsm_x2(tBl + offB, bl);
                    mma_16816(acc[0][n], ah0, bh);
                    mma_16816(acc[0][n], ah0, bl);
                    mma_16816(acc[0][n], al0, bh);
                    mma_16816(acc[1][n], ah1, bh);
                    mma_16816(acc[1][n], ah1, bl);
                    mma_16816(acc[1][n], al1, bh);
                }
            }
            __syncthreads();
        }

        #pragma unroll
        for (int mi = 0; mi < 2; mi++) {
            #pragma unroll
            for (int rr = 0; rr < 2; rr++) {
                int m = bm2 + wm + mi * 16 + (lid >> 2) + rr * 8;
                #pragma unroll
                for (int n = 0; n < 8; n++) {
                    int j0 = bn + wn + n * 8 + (lid & 3) * 2;
                    float v0 = acc[mi][n][rr * 2 + 0] + __ldg(&bias[j0]);
                    float v1 = acc[mi][n][rr * 2 + 1] + __ldg(&bias[j0 + 1]);
                    if (EPI == 1 || EPI == 3) {
                        if (EPI == 1) { v0 = fmaxf(v0, 0.f); v1 = fmaxf(v1, 0.f); }
                        __nv_bfloat16 h0 = __float2bfloat16(v0);
                        __nv_bfloat16 h1 = __float2bfloat16(v1);
                        Chi[(size_t)m * N + j0]     = h0;
                        Chi[(size_t)m * N + j0 + 1] = h1;
                        Clo[(size_t)m * N + j0]     = __float2bfloat16(v0 - __bfloat162float(h0));
                        Clo[(size_t)m * N + j0 + 1] = __float2bfloat16(v1 - __bfloat162float(h1));
                    } else {
                        if (EPI == 2) {
                            v0 = res[(size_t)m * N + j0]     + scl * v0;
                            v1 = res[(size_t)m * N + j0 + 1] + scl * v1;
                        }
                        *(float2*)(C + (size_t)m * N + j0) = make_float2(v0, v1);
                    }
                }
            }
        }
        __syncthreads();
    }
#endif
}

template<int EPI>
__global__ __launch_bounds__(256) void gemm_tc(
    const __nv_bfloat16* __restrict__ Ah, const __nv_bfloat16* __restrict__ Al,
    const __nv_bfloat16* __restrict__ Bh, const __nv_bfloat16* __restrict__ Bl,
    const float* __restrict__ bias, const float* __restrict__ res,
    const float* __restrict__ rs_ptr,
    float* __restrict__ C, __nv_bfloat16* __restrict__ Chi, __nv_bfloat16* __restrict__ Clo,
    int M, int N, int K)
{
    extern __shared__ char smem[];
    int bm = blockIdx.y * 256, bn = blockIdx.x * 128;
    gemm_body<EPI>(smem, smem_to_u32(smem), threadIdx.x,
        Ah + (size_t)bm * K, Al + (size_t)bm * K,
        Bh + (size_t)bn * K, Bl + (size_t)bn * K,
        bias, res, rs_ptr, C, Chi, Clo, bm, bn, N, K);
}

// merged QKV: grid.x = 24 (which = bx>>3), grid.y = 16 (256-row tiles)
__global__ __launch_bounds__(256) void gemm_qkv(
    const __nv_bfloat16* __restrict__ Ah, const __nv_bfloat16* __restrict__ Al,
    const __nv_bfloat16* __restrict__ wqh, const __nv_bfloat16* __restrict__ wql,
    const __nv_bfloat16* __restrict__ wkh, const __nv_bfloat16* __restrict__ wkl,
    const __nv_bfloat16* __restrict__ wvh, const __nv_bfloat16* __restrict__ wvl,
    const float* __restrict__ bq, const float* __restrict__ bk, const float* __restrict__ bv,
    __nv_bfloat16* __restrict__ qh, __nv_bfloat16* __restrict__ ql,
    __nv_bfloat16* __restrict__ kh, __nv_bfloat16* __restrict__ kl,
    __nv_bfloat16* __restrict__ vh, __nv_bfloat16* __restrict__ vl)
{
    extern __shared__ char smem[];
    int which = blockIdx.x >> 3;
    int bn = (blockIdx.x & 7) * 128, bm = blockIdx.y * 256;
    const __nv_bfloat16* Bh = (which == 0) ? wqh : (which == 1) ? wkh : wvh;
    const __nv_bfloat16* Bl = (which == 0) ? wql : (which == 1) ? wkl : wvl;
    const float* bias       = (which == 0) ? bq  : (which == 1) ? bk  : bv;
    __nv_bfloat16* Chi      = (which == 0) ? qh  : (which == 1) ? kh  : vh;
    __nv_bfloat16* Clo      = (which == 0) ? ql  : (which == 1) ? kl  : vl;
    gemm_body<3>(smem, smem_to_u32(smem), threadIdx.x,
        Ah + (size_t)bm * DM, Al + (size_t)bm * DM,
        Bh + (size_t)bn * DM, Bl + (size_t)bn * DM,
        bias, nullptr, nullptr, nullptr, Chi, Clo, bm, bn, DM, DM);
}

// ================ tensor-core causal relu-attention =========================
// v5: far-tile fast path (uniform rel-bias, no per-element mask/clip/LDS)
// + bf16x2 single-cvt repack. Bit-exact vs v3.
#define AT_SQH 0
#define AT_SQL 16384
#define AT_KV(s) (32768 + (s) * 32768)
#define AT_SRE 98304
#define AT_TOTAL (98304 + 1024)

__global__ __launch_bounds__(256) void attn_tc_kernel(
    const __nv_bfloat16* __restrict__ Qh, const __nv_bfloat16* __restrict__ Ql,
    const __nv_bfloat16* __restrict__ Kh, const __nv_bfloat16* __restrict__ Kl,
    const __nv_bfloat16* __restrict__ Vh, const __nv_bfloat16* __restrict__ Vl,
    const float* __restrict__ RE,
    __nv_bfloat16* __restrict__ Oh, __nv_bfloat16* __restrict__ Ol)
{
    extern __shared__ char sm[];
    uint32_t sb = smem_to_u32(sm);
    float* sre = (float*)(sm + AT_SRE);
    int tid = threadIdx.x, wid = tid >> 5, lid = tid & 31;
    int qt = (int)gridDim.x - 1 - (int)blockIdx.x;   // heavy tiles first
    int h = blockIdx.y, b = blockIdx.z;
    size_t base = ((size_t)b * TS) * DM + h * DH;
    int Q0 = qt * 128;

    if (tid < 255) sre[tid] = RE[tid * NH + h];

    auto loadKV_async = [&](int kt, int s) {
        uint32_t kb = sb + AT_KV(s);
        #pragma unroll
        for (int i = 0; i < 2; i++) {
            int idx = i * 256 + tid; int r = idx >> 3, c8 = idx & 7;
            size_t g = base + (size_t)(kt * 64 + r) * DM + c8 * 8;
            uint32_t off = SMEM_SWIZZLE_128B((uint32_t)(r * 128 + c8 * 16));
            CP_ASYNC16(kb + 0     + off, Kh + g);
            CP_ASYNC16(kb + 8192  + off, Kl + g);
            CP_ASYNC16(kb + 16384 + off, Vh + g);
            CP_ASYNC16(kb + 24576 + off, Vl + g);
        }
    };

    loadKV_async(0, 0); CP_COMMIT();

    #pragma unroll
    for (int i = 0; i < 4; i++) {
        int idx = i * 256 + tid; int r = idx >> 3, c8 = idx & 7;
        size_t g = base + (size_t)(Q0 + r) * DM + c8 * 8;
        uint32_t off = SMEM_SWIZZLE_128B((uint32_t)(r * 128 + c8 * 16));
        *(uint4*)(sm + AT_SQH + off) = *(const uint4*)(Qh + g);
        *(uint4*)(sm + AT_SQL + off) = *(const uint4*)(Ql + g);
    }
    CP_WAIT0();
    __syncthreads();

    uint32_t qa_h[4][4], qa_l[4][4];
    {
        int amat = lid >> 3;
        int arow = (lid & 7) + ((amat & 1) << 3);
        int acol = (amat >> 1) << 4;
        #pragma unroll
        for (int kk = 0; kk < 4; kk++) {
            uint32_t off = SMEM_SWIZZLE_128B((uint32_t)((wid * 16 + arow) * 128 + kk * 32 + acol));
            ldsm_x4(sb + AT_SQH + off, qa_h[kk]);
            ldsm_x4(sb + AT_SQL + off, qa_l[kk]);
        }
    }

    float acc[8][4];
    #pragma unroll
    for (int dn = 0; dn < 8; dn++)
        #pragma unroll
        for (int q = 0; q < 4; q++) acc[dn][q] = 0.f;
    float rs0 = 0.f, rs1 = 0.f;
    int g4 = lid >> 2, tg = lid & 3;
    int qrow0 = Q0 + wid * 16 + g4;
    int qmax  = Q0 + wid * 16 + 15;
    int wqbase = Q0 + wid * 16;

    int r1 = ((lid >> 4) & 1) * 8 + (lid & 7);
    int c1 = ((lid >> 3) & 1) << 4;
    int r2 = (((lid >> 3) & 1) << 3) + (lid & 7);
    int c2 = ((lid >> 4) & 1) << 4;

    const float c0 = sre[0];
    const int KT = 2 * qt + 2;
    for (int kt = 0; kt < KT; kt++) {
        int s = kt & 1;
        if (kt + 1 < KT) { loadKV_async(kt + 1, s ^ 1); CP_COMMIT(); }

        if (kt * 64 <= qmax) {
            uint32_t kvb = sb + AT_KV(s);
            bool far = (kt * 64 + 63 <= wqbase - 127);

            float sv_[8][4];
            #pragma unroll
            for (int np = 0; np < 4; np++) {
                sv_[2*np][0] = sv_[2*np][1] = sv_[2*np][2] = sv_[2*np][3] = 0.f;
                sv_[2*np+1][0] = sv_[2*np+1][1] = sv_[2*np+1][2] = sv_[2*np+1][3] = 0.f;
                #pragma unroll
                for (int kk = 0; kk < 4; kk++) {
                    uint32_t off = SMEM_SWIZZLE_128B(
                        (uint32_t)((np * 16 + r1) * 128 + kk * 32 + c1));
                    uint32_t rh[4], rl[4];
                    ldsm_x4(kvb + 0    + off, rh);
                    ldsm_x4(kvb + 8192 + off, rl);
                    mma_16816(sv_[2*np],   qa_h[kk], rh);
                    mma_16816(sv_[2*np],   qa_h[kk], rl);
                    mma_16816(sv_[2*np],   qa_l[kk], rh);
                    mma_16816(sv_[2*np+1], qa_h[kk], rh + 2);
                    mma_16816(sv_[2*np+1], qa_h[kk], rl + 2);
                    mma_16816(sv_[2*np+1], qa_l[kk], rh + 2);
                }
            }

            uint32_t wh[4][4], wl[4][4];
            #pragma unroll
            for (int n = 0; n < 8; n++) {
                float wv[4];
                if (far) {
                    #pragma unroll
                    for (int e = 0; e < 4; e++)
                        wv[e] = fmaxf(sv_[n][e] * 0.125f + c0, 0.f) + 1e-6f;
                } else {
                    int kc0 = kt * 64 + n * 8 + tg * 2;
                    #pragma unroll
                    for (int e = 0; e < 4; e++) {
                        int kg = kc0 + (e & 1);
                        int qg = qrow0 + ((e >> 1) << 3);
                        int rel = kg - qg;
                        int rc = (rel < -127 ? -127 : (rel > 127 ? 127 : rel)) + 127;
                        float sv = sv_[n][e] * 0.125f + sre[rc];
                        wv[e] = (kg <= qg) ? (fmaxf(sv, 0.f) + 1e-6f) : 0.f;
                    }
                }
                rs0 += wv[0] + wv[1];
                rs1 += wv[2] + wv[3];
                int kk = n >> 1, a0 = (n & 1) << 1;
                uint32_t hp01 = cvt_bf16x2(wv[0], wv[1]);
                uint32_t hp23 = cvt_bf16x2(wv[2], wv[3]);
                float h0 = __uint_as_float(hp01 << 16);
                float h1 = __uint_as_float(hp01 & 0xffff0000u);
                float h2 = __uint_as_float(hp23 << 16);
                float h3 = __uint_as_float(hp23 & 0xffff0000u);
                wh[kk][a0 + 0] = hp01;
                wh[kk][a0 + 1] = hp23;
                wl[kk][a0 + 0] = cvt_bf16x2(wv[0] - h0, wv[1] - h1);
                wl[kk][a0 + 1] = cvt_bf16x2(wv[2] - h2, wv[3] - h3);
            }

            #pragma unroll
            for (int kk = 0; kk < 4; kk++) {
                #pragma unroll
                for (int dp = 0; dp < 4; dp++) {
                    uint32_t off = SMEM_SWIZZLE_128B(
                        (uint32_t)((kk * 16 + r2) * 128 + dp * 32 + c2));
                    uint32_t vh4[4], vl4[4];
                    ldsm_x4_trans(kvb + 16384 + off, vh4);
                    ldsm_x4_trans(kvb + 24576 + off, vl4);
                    mma_16816(acc[2*dp],   wh[kk], vh4);
                    mma_16816(acc[2*dp],   wh[kk], vl4);
                    mma_16816(acc[2*dp],   wl[kk], vh4);
                    mma_16816(acc[2*dp+1], wh[kk], vh4 + 2);
                    mma_16816(acc[2*dp+1], wh[kk], vl4 + 2);
                    mma_16816(acc[2*dp+1], wl[kk], vh4 + 2);
                }
            }
        }
        CP_WAIT0();
        __syncthreads();
    }

    rs0 += __shfl_xor_sync(0xffffffffu, rs0, 1);
    rs0 += __shfl_xor_sync(0xffffffffu, rs0, 2);
    rs1 += __shfl_xor_sync(0xffffffffu, rs1, 1);
    rs1 += __shfl_xor_sync(0xffffffffu, rs1, 2);
    float inv0 = 1.f / (rs0 + 1e-6f);
    float inv1 = 1.f / (rs1 + 1e-6f);

    #pragma unroll
    for (int dn = 0; dn < 8; dn++) {
        float v0 = acc[dn][0] * inv0, v1 = acc[dn][1] * inv0;
        float v2 = acc[dn][2] * inv1, v3 = acc[dn][3] * inv1;
        size_t o0 = base + (size_t)qrow0 * DM + dn * 8 + tg * 2;
        size_t o1 = o0 + (size_t)8 * DM;
        uint32_t p01 = cvt_bf16x2(v0, v1);
        uint32_t p23 = cvt_bf16x2(v2, v3);
        float h0 = __uint_as_float(p01 << 16);
        float h1 = __uint_as_float(p01 & 0xffff0000u);
        float h2 = __uint_as_float(p23 << 16);
        float h3 = __uint_as_float(p23 & 0xffff0000u);
        *(uint32_t*)(Oh + o0) = p01;
        *(uint32_t*)(Oh + o1) = p23;
        *(uint32_t*)(Ol + o0) = cvt_bf16x2(v0 - h0, v1 - h1);
        *(uint32_t*)(Ol + o1) = cvt_bf16x2(v2 - h2, v3 - h3);
    }
}

// ---------------- driver ----------------------------------------------------
extern "C" void kernel_launch(void* const* d_in, const int* in_sizes, int n_in,
                              void* d_out, int out_size)
{
    const float* x   = (const float*)d_in[0];
    const float* Wq  = (const float*)d_in[2];
    const float* bq  = (const float*)d_in[3];
    const float* Wk  = (const float*)d_in[4];
    const float* bk  = (const float*)d_in[5];
    const float* Wv  = (const float*)d_in[6];
    const float* bv  = (const float*)d_in[7];
    const float* Wo  = (const float*)d_in[8];
    const float* bo  = (const float*)d_in[9];
    const float* re  = (const float*)d_in[10];
    const float* g1  = (const float*)d_in[11];
    const float* be1 = (const float*)d_in[12];
    const float* a1  = (const float*)d_in[13];
    const float* br1 = (const float*)d_in[14];
    const float* g2  = (const float*)d_in[15];
    const float* be2 = (const float*)d_in[16];
    const float* a2  = (const float*)d_in[17];
    const float* br2 = (const float*)d_in[18];
    const float* W1  = (const float*)d_in[19];
    const float* b1  = (const float*)d_in[20];
    const float* W2  = (const float*)d_in[21];
    const float* b2  = (const float*)d_in[22];
    const float* rs  = (const float*)d_in[23];
    float* out = (float*)d_out;

    float *px1;
    cudaGetSymbolAddress((void**)&px1,  g_x1);
    __nv_bfloat16 *lnh,*lnl,*qh,*ql,*kbh,*kbl,*vbh,*vbl,*ath,*atl,*hh,*hl,*fh,*fl;
    __nv_bfloat16 *wqh,*wql,*wkh,*wkl,*wvh,*wvl,*woh,*wol,*w1h,*w1l,*w2h,*w2l;
    cudaGetSymbolAddress((void**)&lnh, g_lnh); cudaGetSymbolAddress((void**)&lnl, g_lnl);
    cudaGetSymbolAddress((void**)&qh,  g_qh ); cudaGetSymbolAddress((void**)&ql,  g_ql );
    cudaGetSymbolAddress((void**)&kbh, g_kbh); cudaGetSymbolAddress((void**)&kbl, g_kbl);
    cudaGetSymbolAddress((void**)&vbh, g_vbh); cudaGetSymbolAddress((void**)&vbl, g_vbl);
    cudaGetSymbolAddress((void**)&ath, g_ath); cudaGetSymbolAddress((void**)&atl, g_atl);
    cudaGetSymbolAddress((void**)&hh,  g_hh ); cudaGetSymbolAddress((void**)&hl,  g_hl );
    cudaGetSymbolAddress((void**)&fh,  g_fh ); cudaGetSymbolAddress((void**)&fl,  g_fl );
    cudaGetSymbolAddress((void**)&wqh, g_wqh); cudaGetSymbolAddress((void**)&wql, g_wql);
    cudaGetSymbolAddress((void**)&wkh, g_wkh); cudaGetSymbolAddress((void**)&wkl, g_wkl);
    cudaGetSymbolAddress((void**)&wvh, g_wvh); cudaGetSymbolAddress((void**)&wvl, g_wvl);
    cudaGetSymbolAddress((void**)&woh, g_woh); cudaGetSymbolAddress((void**)&wol, g_wol);
    cudaGetSymbolAddress((void**)&w1h, g_w1h); cudaGetSymbolAddress((void**)&w1l, g_w1l);
    cudaGetSymbolAddress((void**)&w2h, g_w2h); cudaGetSymbolAddress((void**)&w2l, g_w2l);

    cudaFuncSetAttribute(gemm_tc<1>, cudaFuncAttributeMaxDynamicSharedMemorySize, G_SM_TOTAL);
    cudaFuncSetAttribute(gemm_tc<2>, cudaFuncAttributeMaxDynamicSharedMemorySize, G_SM_TOTAL);
    cudaFuncSetAttribute(gemm_qkv,   cudaFuncAttributeMaxDynamicSharedMemorySize, G_SM_TOTAL);
    cudaFuncSetAttribute(attn_tc_kernel, cudaFuncAttributeMaxDynamicSharedMemorySize, AT_TOTAL);

    // 0: all weight splits fused
    split6_kernel<<<dim3(1024, 6), 256>>>(
        Wq, Wk, Wv, Wo, W1, W2,
        wqh, wql, wkh, wkl, wvh, wvl, woh, wol, w1h, w1l, w2h, w2l);

    // 1: ln1 -> bf16 hi/lo
    ln_kernel<<<NT, 256>>>(x, g1, be1, a1, br1, lnh, lnl);

    // 2: merged QKV projections (256-row tiles) -> bf16 hi/lo
    gemm_qkv<<<dim3(24, NT / 256), 256, G_SM_TOTAL>>>(
        lnh, lnl, wqh, wql, wkh, wkl, wvh, wvl,
        bq, bk, bv, qh, ql, kbh, kbl, vbh, vbl);

    // 3: attention v5 -> bf16 hi/lo
    attn_tc_kernel<<<dim3(TS / 128, NH, NB), 256, AT_TOTAL>>>(
        qh, ql, kbh, kbl, vbh, vbl, re, ath, atl);

    // 4: O projection + residual
    gemm_tc<2><<<dim3(DM / 128, NT / 256), 256, G_SM_TOTAL>>>(
        ath, atl, woh, wol, bo, x, rs, px1, nullptr, nullptr, NT, DM, DM);

    // 5: ln2 -> bf16 hi/lo
    ln_kernel<<<NT, 256>>>(px1, g2, be2, a2, br2, hh, hl);

    // 6: FFN1 (relu) -> bf16 hi/lo
    gemm_tc<1><<<dim3(DF / 128, NT / 256), 256, G_SM_TOTAL>>>(
        hh, hl, w1h, w1l, b1, nullptr, nullptr, nullptr, fh, fl, NT, DF, DM);

    // 7: FFN2 + residual -> out
    gemm_tc<2><<<dim3(DM / 128, NT / 256), 256, G_SM_TOTAL>>>(
        fh, fl, w2h, w2l, b2, px1, rs, out, nullptr, nullptr, NT, DM, DF);
}

// round 16
// speedup vs baseline: 1.3500x; 1.1075x over previous
#include <cuda_runtime.h>
#include <cuda_bf16.h>
#include <math.h>
#include <stdint.h>

#define DM 1024
#define TS 2048
#define NB 2
#define NH 16
#define DH 64
#define DF 4096
#define NT (NB*TS)   // 4096 tokens

// ---------------- scratch (static __device__, no allocations) ----------------
__device__ float g_x1  [(size_t)NT*DM];

__device__ __nv_bfloat16 g_lnh [(size_t)NT*DM];
__device__ __nv_bfloat16 g_lnl [(size_t)NT*DM];
__device__ __nv_bfloat16 g_qh  [(size_t)NT*DM], g_ql [(size_t)NT*DM];
__device__ __nv_bfloat16 g_kbh [(size_t)NT*DM], g_kbl[(size_t)NT*DM];
__device__ __nv_bfloat16 g_vbh [(size_t)NT*DM], g_vbl[(size_t)NT*DM];
__device__ __nv_bfloat16 g_ath [(size_t)NT*DM];
__device__ __nv_bfloat16 g_atl [(size_t)NT*DM];
__device__ __nv_bfloat16 g_hh  [(size_t)NT*DM];
__device__ __nv_bfloat16 g_hl  [(size_t)NT*DM];
__device__ __nv_bfloat16 g_fh  [(size_t)NT*DF];
__device__ __nv_bfloat16 g_fl  [(size_t)NT*DF];
__device__ __nv_bfloat16 g_wqh[(size_t)DM*DM], g_wql[(size_t)DM*DM];
__device__ __nv_bfloat16 g_wkh[(size_t)DM*DM], g_wkl[(size_t)DM*DM];
__device__ __nv_bfloat16 g_wvh[(size_t)DM*DM], g_wvl[(size_t)DM*DM];
__device__ __nv_bfloat16 g_woh[(size_t)DM*DM], g_wol[(size_t)DM*DM];
__device__ __nv_bfloat16 g_w1h[(size_t)DF*DM], g_w1l[(size_t)DF*DM];
__device__ __nv_bfloat16 g_w2h[(size_t)DM*DF], g_w2l[(size_t)DM*DF];

// ===================== helpers ==============================================
__device__ __forceinline__ uint32_t smem_to_u32(const void* p) {
    uint32_t a;
    asm("{ .reg .u64 t; cvta.to.shared.u64 t, %1; cvt.u32.u64 %0, t; }" : "=r"(a) : "l"(p));
    return a;
}
#define SMEM_SWIZZLE_128B(byte_offset) ((byte_offset) ^ (((byte_offset) >> 3) & 0x70))
#define SMEM_SWIZZLE_64B(byte_offset)  ((byte_offset) ^ (((byte_offset) >> 3) & 0x30))

__device__ __forceinline__ uint32_t pack_bf16(float lo, float hi) {
    __nv_bfloat162 p(__float2bfloat16(lo), __float2bfloat16(hi));
    return *(uint32_t*)&p;
}
// pack pair with single cvt (identical RN rounding): low = a, high = b
__device__ __forceinline__ uint32_t cvt_bf16x2(float a, float b) {
    uint32_t r;
    asm("cvt.rn.bf16x2.f32 %0, %1, %2;" : "=r"(r) : "f"(b), "f"(a));
    return r;
}

#define CP_ASYNC16(dst_smem, src_gptr) \
    asm volatile("cp.async.cg.shared.global [%0], [%1], 16;" \
        :: "r"((uint32_t)(dst_smem)), "l"(src_gptr) : "memory")
#define CP_COMMIT() asm volatile("cp.async.commit_group;" ::: "memory")
#define CP_WAIT0()  asm volatile("cp.async.wait_group 0;" ::: "memory")
#define CP_WAIT1()  asm volatile("cp.async.wait_group 1;" ::: "memory")

// ---- sm_80+ baseline tensor-core ops (always available) --------------------
__device__ __forceinline__ void ldsm_x4(uint32_t addr, uint32_t* r) {
    asm volatile("ldmatrix.sync.aligned.m8n8.x4.shared.b16 {%0,%1,%2,%3}, [%4];"
        : "=r"(r[0]), "=r"(r[1]), "=r"(r[2]), "=r"(r[3]) : "r"(addr));
}
__device__ __forceinline__ void ldsm_x2(uint32_t addr, uint32_t* r) {
    asm volatile("ldmatrix.sync.aligned.m8n8.x2.shared.b16 {%0,%1}, [%2];"
        : "=r"(r[0]), "=r"(r[1]) : "r"(addr));
}
__device__ __forceinline__ void ldsm_x4_trans(uint32_t addr, uint32_t* r) {
    asm volatile("ldmatrix.sync.aligned.m8n8.x4.trans.shared.b16 {%0,%1,%2,%3}, [%4];"
        : "=r"(r[0]), "=r"(r[1]), "=r"(r[2]), "=r"(r[3]) : "r"(addr));
}
__device__ __forceinline__ void mma_16816(float* d, const uint32_t* a, const uint32_t* b) {
    asm volatile("mma.sync.aligned.m16n8k16.row.col.f32.bf16.bf16.f32 "
        "{%0,%1,%2,%3}, {%4,%5,%6,%7}, {%8,%9}, {%0,%1,%2,%3};"
        : "+f"(d[0]), "+f"(d[1]), "+f"(d[2]), "+f"(d[3])
        : "r"(a[0]), "r"(a[1]), "r"(a[2]), "r"(a[3]), "r"(b[0]), "r"(b[1]));
}

// ---- tcgen05 path (only compiled when the sm_103a feature set is present) --
#if defined(__CUDA_ARCH_FEAT_SM103_ALL)
#define HAVE_TC5 1
__device__ __forceinline__ uint32_t elect_one_pred() {
    uint32_t pred;
    asm volatile("{\n\t.reg .pred p;\n\telect.sync _|p, 0xFFFFFFFF;\n\tselp.b32 %0, 1, 0, p;\n\t}" : "=r"(pred));
    return pred;
}
#define MBARRIER_INIT(addr, cnt) \
    asm volatile("mbarrier.init.shared.b64 [%0], %1;" :: "r"((uint32_t)(addr)), "r"((uint32_t)(cnt)) : "memory")
#define MBARRIER_INVAL(addr) \
    asm volatile("mbarrier.inval.shared.b64 [%0];" :: "r"((uint32_t)(addr)) : "memory")
#define MBARRIER_WAIT_PARITY(mbar_smem_addr, phase_parity) do { \
    uint32_t _mbar = (uint32_t)(mbar_smem_addr); \
    uint32_t _parity = (uint32_t)(phase_parity); \
    uint32_t _done; \
    asm volatile("{\n\t.reg .pred p;\n\tmbarrier.try_wait.parity.acquire.cta.shared::cta.b64 p, [%1], %2;\n\tselp.b32 %0, 1, 0, p;\n\t}" \
        : "=r"(_done) : "r"(_mbar), "r"(_parity) : "memory"); \
    if (!_done) { \
        asm volatile("{\n\t.reg .pred P1;\n\tWAIT_LOOP_%=:\n\tmbarrier.try_wait.parity.acquire.cta.shared::cta.b64 P1, [%0], %1, 0x989680;\n\t@P1 bra.uni WAIT_DONE_%=;\n\tbra.uni WAIT_LOOP_%=;\n\tWAIT_DONE_%=:\n\t}" \
            :: "r"(_mbar), "r"(_parity) : "memory"); \
    } \
} while(0)
#define TCGEN05_ALLOC(smem_result_addr, nCols) \
    asm volatile("tcgen05.alloc.cta_group::1.sync.aligned.shared::cta.b32 [%0], %1;" \
        :: "r"((uint32_t)(smem_result_addr)), "r"((uint32_t)(nCols)) : "memory")
#define TCGEN05_DEALLOC(tmem_addr, nCols) \
    asm volatile("tcgen05.dealloc.cta_group::1.sync.aligned.b32 %0, %1;" :: "r"(tmem_addr), "r"((uint32_t)(nCols)))
#define TCGEN05_COMMIT(mbar_smem_addr) \
    asm volatile("tcgen05.commit.cta_group::1.mbarrier::arrive::one.shared::cluster.b64 [%0];" \
        :: "r"((uint32_t)(mbar_smem_addr)) : "memory")
#define TCGEN05_WAIT_LD()  asm volatile("tcgen05.wait::ld.sync.aligned;" ::: "memory")
#define TCGEN05_FENCE_AFTER()  asm volatile("tcgen05.fence::after_thread_sync;" ::: "memory")
#define TCGEN05_FENCE_BEFORE() asm volatile("tcgen05.fence::before_thread_sync;" ::: "memory")
#define TCGEN05_LD_32X32B_X32(r, tmem_addr) \
    asm volatile("tcgen05.ld.sync.aligned.32x32b.x32.b32 " \
        "{%0, %1, %2, %3, %4, %5, %6, %7, %8, %9, %10, %11, %12, %13, %14, %15, " \
        " %16, %17, %18, %19, %20, %21, %22, %23, %24, %25, %26, %27, %28, %29, %30, %31}, [%32];" \
        : "=r"((r)[0]),  "=r"((r)[1]),  "=r"((r)[2]),  "=r"((r)[3]), \
          "=r"((r)[4]),  "=r"((r)[5]),  "=r"((r)[6]),  "=r"((r)[7]), \
          "=r"((r)[8]),  "=r"((r)[9]),  "=r"((r)[10]), "=r"((r)[11]), \
          "=r"((r)[12]), "=r"((r)[13]), "=r"((r)[14]), "=r"((r)[15]), \
          "=r"((r)[16]), "=r"((r)[17]), "=r"((r)[18]), "=r"((r)[19]), \
          "=r"((r)[20]), "=r"((r)[21]), "=r"((r)[22]), "=r"((r)[23]), \
          "=r"((r)[24]), "=r"((r)[25]), "=r"((r)[26]), "=r"((r)[27]), \
          "=r"((r)[28]), "=r"((r)[29]), "=r"((r)[30]), "=r"((r)[31]) \
        : "r"(tmem_addr))

static constexpr uint64_t SMEM_DESC_BASE_SW128 =
    (uint64_t(2)  << 61) | (uint64_t(1) << 46) | (uint64_t(64) << 32) | (uint64_t(1) << 16);
#define MAKE_SMEM_DESC(base_addr) (SMEM_DESC_BASE_SW128 | ((uint64_t)((base_addr) >> 4) & 0x3FFF))
// SW64: layout=4, version=1 (Blackwell), SBO=32 (512B = 8 rows x 64B), LBO=1
static constexpr uint64_t SMEM_DESC_BASE_SW64 =
    (uint64_t(4)  << 61) | (uint64_t(1) << 46) | (uint64_t(32) << 32) | (uint64_t(1) << 16);
#define MAKE_SMEM_DESC64(base_addr) (SMEM_DESC_BASE_SW64 | ((uint64_t)((base_addr) >> 4) & 0x3FFF))

// idesc: D=f32, A=BF16, B=BF16, M=128, N=128, K-major both
static constexpr uint32_t IDESC_BF16_128x128 =
    (1u << 4) | (1u << 7) | (1u << 10) | ((128u / 8u) << 17) | ((128u / 16u) << 24);

__device__ __forceinline__ void mma_bf16_ss(uint32_t d, uint64_t a, uint64_t b, uint32_t en) {
    asm volatile(
        "{\n\t.reg .pred p;\n\tsetp.ne.u32 p, %4, 0;\n\t"
        "tcgen05.mma.cta_group::1.kind::f16 [%0], %1, %2, %3, {%5, %5, %5, %5}, p;\n\t}"
        :: "r"(d), "l"(a), "l"(b), "r"(IDESC_BF16_128x128), "r"(en), "r"(0u)
        : "memory");
}
#else
#define HAVE_TC5 0
#endif

// ===================== misc math ============================================
__device__ __forceinline__ float softplus10(float br) {
    float t = 10.f * br;
    float sp = (t > 20.f) ? t : log1pf(expf(t));
    return sp * 0.1f;
}

// ---------------- fused fp32 -> bf16 hi/lo split (6 arrays) ------------------
__global__ __launch_bounds__(256) void split6_kernel(
    const float* __restrict__ s0, const float* __restrict__ s1,
    const float* __restrict__ s2, const float* __restrict__ s3,
    const float* __restrict__ s4, const float* __restrict__ s5,
    __nv_bfloat16* __restrict__ h0, __nv_bfloat16* __restrict__ l0,
    __nv_bfloat16* __restrict__ h1, __nv_bfloat16* __restrict__ l1,
    __nv_bfloat16* __restrict__ h2, __nv_bfloat16* __restrict__ l2,
    __nv_bfloat16* __restrict__ h3, __nv_bfloat16* __restrict__ l3,
    __nv_bfloat16* __restrict__ h4, __nv_bfloat16* __restrict__ l4,
    __nv_bfloat16* __restrict__ h5, __nv_bfloat16* __restrict__ l5)
{
    int seg = blockIdx.y;
    const float* X; __nv_bfloat16 *H, *L; int n4;
    switch (seg) {
        case 0:  X = s0; H = h0; L = l0; n4 = DM * DM / 4; break;
        case 1:  X = s1; H = h1; L = l1; n4 = DM * DM / 4; break;
        case 2:  X = s2; H = h2; L = l2; n4 = DM * DM / 4; break;
        case 3:  X = s3; H = h3; L = l3; n4 = DM * DM / 4; break;
        case 4:  X = s4; H = h4; L = l4; n4 = DF * DM / 4; break;
        default: X = s5; H = h5; L = l5; n4 = DF * DM / 4; break;
    }
    for (int i = blockIdx.x * 256 + threadIdx.x; i < n4; i += gridDim.x * 256) {
        float4 v = ((const float4*)X)[i];
        float h0f = __bfloat162float(__float2bfloat16(v.x));
        float h1f = __bfloat162float(__float2bfloat16(v.y));
        float h2f = __bfloat162float(__float2bfloat16(v.z));
        float h3f = __bfloat162float(__float2bfloat16(v.w));
        uint2 hp = make_uint2(pack_bf16(h0f, h1f), pack_bf16(h2f, h3f));
        uint2 lp = make_uint2(pack_bf16(v.x - h0f, v.y - h1f), pack_bf16(v.z - h2f, v.w - h3f));
        *(uint2*)(H + (size_t)i * 4) = hp;
        *(uint2*)(L + (size_t)i * 4) = lp;
    }
}

// ---------------- algebraic layernorm -> bf16 hi/lo --------------------------
__global__ __launch_bounds__(256) void ln_kernel(
    const float* __restrict__ X, const float* __restrict__ g,
    const float* __restrict__ be, const float* __restrict__ a,
    const float* __restrict__ br,
    __nv_bfloat16* __restrict__ YH, __nv_bfloat16* __restrict__ YL)
{
    int row = blockIdx.x;
    const float* x = X + (size_t)row * DM;
    float v[4]; float sum = 0.f, sq = 0.f;
    #pragma unroll
    for (int i = 0; i < 4; i++) {
        v[i] = x[threadIdx.x + i * 256];
        sum += v[i]; sq += v[i] * v[i];
    }
    #pragma unroll
    for (int o = 16; o > 0; o >>= 1) {
        sum += __shfl_down_sync(0xffffffffu, sum, o);
        sq  += __shfl_down_sync(0xffffffffu, sq,  o);
    }
    __shared__ float s1[8], s2[8];
    int w = threadIdx.x >> 5, lane = threadIdx.x & 31;
    if (lane == 0) { s1[w] = sum; s2[w] = sq; }
    __syncthreads();
    if (threadIdx.x == 0) {
        float A = 0.f, B = 0.f;
        #pragma unroll
        for (int i = 0; i < 8; i++) { A += s1[i]; B += s2[i]; }
        s1[0] = A; s2[0] = B;
    }
    __syncthreads();
    float mean = s1[0] * (1.f / DM);
    float var  = s2[0] * (1.f / DM) - mean * mean;
    float z = var + 1e-5f;
    float p = a[0] + a[1] * z + a[2] * z * z;
    float b0 = softplus10(br[0]), b1 = softplus10(br[1]), b2 = softplus10(br[2]);
    float q = b0 + b1 * z + b2 * z * z;
    float fac = p / q;
    #pragma unroll
    for (int i = 0; i < 4; i++) {
        int c = threadIdx.x + i * 256;
        float y = (v[i] - mean) * fac * g[c] + be[c];
        __nv_bfloat16 h = __float2bfloat16(y);
        __nv_bfloat16 l = __float2bfloat16(y - __bfloat162float(h));
        YH[(size_t)row * DM + c] = h;
        YL[(size_t)row * DM + c] = l;
    }
}

// ===================== tensor-core bf16x3 GEMM (256x128 tiles) ==============
// C[M,N] = epi( A[M,K] @ B[N,K]^T ),  A = Ah+Al, B = Bh+Bl (bf16 splits).
// M-tile = 256, two TMEM accumulators. KC=32 (64B rows, SW64), 4 stages,
// 2-deep cp.async pipeline: MMA(c) commit -> wait MMA(c-1) -> load(c+2) ->
// wait_group 1 (chunk c+1 ready, c+2 in flight).
// EPI: 1 = relu(+bias) -> bf16 hi/lo ; 2 = res + clip(rs)*(+bias) -> f32 ;
//      3 = +bias -> bf16 hi/lo
#define KC2 32
#define G_SM_TPTR 0
#define G_SM_MBAR 8
#define G2_STAGE(s) (1024 + (s) * 49152)      // 48KB per stage, 4 stages
#define G2_AH 0
#define G2_AL 16384
#define G2_BH 32768
#define G2_BL 40960
#define G_SM_TOTAL (1024 + 4 * 49152)          // 197632 B -> 1 CTA/SM

template<int EPI>
__device__ __forceinline__ void gemm_body(
    char* smem, uint32_t sb, int tid,
    const __nv_bfloat16* __restrict__ Ahb, const __nv_bfloat16* __restrict__ Alb,
    const __nv_bfloat16* __restrict__ Bhb, const __nv_bfloat16* __restrict__ Blb,
    const float* __restrict__ bias, const float* __restrict__ res,
    const float* __restrict__ rs_ptr,
    float* __restrict__ C, __nv_bfloat16* __restrict__ Chi, __nv_bfloat16* __restrict__ Clo,
    int bm, int bn, int N, int K)
{
    int wid = tid >> 5, lid = tid & 31;

    float scl = 1.f;
    if (EPI == 2) scl = fminf(fmaxf(*rs_ptr, 0.2f), 1.f);

#if HAVE_TC5
    const int NC = K / KC2;
    if (wid == 0) TCGEN05_ALLOC(sb + G_SM_TPTR, 256);
    __syncthreads();
    uint32_t tmem;
    asm volatile("ld.shared.b32 %0, [%1];" : "=r"(tmem) : "r"(sb + G_SM_TPTR));
    if (tid == 0) MBARRIER_INIT(sb + G_SM_MBAR, 1);
    __syncthreads();

    // async load of one KC2 chunk (A 256 rows, B 128 rows; hi+lo) into stage st
    auto loadAB2 = [&](int c, int st) {
        uint32_t bb = sb + G2_STAGE(st);
        #pragma unroll
        for (int arr = 0; arr < 2; arr++) {          // A: 1024 vec each
            const __nv_bfloat16* src = arr ? Alb : Ahb;
            uint32_t tb = bb + (arr ? G2_AL : G2_AH);
            #pragma unroll
            for (int i = 0; i < 4; i++) {
                int idx = i * 256 + tid;
                int row = idx >> 2, v16 = idx & 3;
                uint32_t off = SMEM_SWIZZLE_64B((uint32_t)(row * 64 + v16 * 16));
                CP_ASYNC16(tb + off, src + (size_t)row * K + c * KC2 + v16 * 8);
            }
        }
        #pragma unroll
        for (int arr = 0; arr < 2; arr++) {          // B: 512 vec each
            const __nv_bfloat16* src = arr ? Blb : Bhb;
            uint32_t tb = bb + (arr ? G2_BL : G2_BH);
            #pragma unroll
            for (int i = 0; i < 2; i++) {
                int idx = i * 256 + tid;
                int row = idx >> 2, v16 = idx & 3;
                uint32_t off = SMEM_SWIZZLE_64B((uint32_t)(row * 64 + v16 * 16));
                CP_ASYNC16(tb + off, src + (size_t)row * K + c * KC2 + v16 * 8);
            }
        }
    };

    // preload chunks 0 and 1 (two commit groups), wait chunk 0 only
    loadAB2(0, 0); CP_COMMIT();
    loadAB2(1, 1); CP_COMMIT();
    CP_WAIT1();
    TCGEN05_FENCE_BEFORE();
    __syncthreads();

    for (int c = 0; c < NC; c++) {
        int s = c & 3;
        if (wid == 0) {
            TCGEN05_FENCE_AFTER();
            if (elect_one_pred()) {
                uint32_t bb = sb + G2_STAGE(s);
                uint64_t dah0 = MAKE_SMEM_DESC64(bb + G2_AH);
                uint64_t dah1 = MAKE_SMEM_DESC64(bb + G2_AH + 8192);
                uint64_t dal0 = MAKE_SMEM_DESC64(bb + G2_AL);
                uint64_t dal1 = MAKE_SMEM_DESC64(bb + G2_AL + 8192);
                uint64_t dbh  = MAKE_SMEM_DESC64(bb + G2_BH);
                uint64_t dbl  = MAKE_SMEM_DESC64(bb + G2_BL);
                #pragma unroll
                for (int ks = 0; ks < KC2 / 16; ks++) {
                    uint32_t en0 = (c == 0 && ks == 0) ? 0u : 1u;
                    mma_bf16_ss(tmem,       dah0 + ks * 2, dbh + ks * 2, en0);
                    mma_bf16_ss(tmem,       dah0 + ks * 2, dbl + ks * 2, 1u);
                    mma_bf16_ss(tmem,       dal0 + ks * 2, dbh + ks * 2, 1u);
                    mma_bf16_ss(tmem + 128, dah1 + ks * 2, dbh + ks * 2, en0);
                    mma_bf16_ss(tmem + 128, dah1 + ks * 2, dbl + ks * 2, 1u);
                    mma_bf16_ss(tmem + 128, dal1 + ks * 2, dbh + ks * 2, 1u);
                }
                TCGEN05_COMMIT(sb + G_SM_MBAR);
            }
        }
        // wait MMA(c-1): frees stage (c+3)&3 = (c+2)&3's predecessor readers
        if (c >= 1) MBARRIER_WAIT_PARITY(sb + G_SM_MBAR, (c - 1) & 1);
        if (c + 2 < NC) {
            loadAB2(c + 2, (c + 2) & 3);   // last reader MMA(c-2), done
            CP_COMMIT();
            CP_WAIT1();                    // chunk c+1 complete; c+2 in flight
        } else {
            CP_WAIT0();                    // tail: drain remaining group(s)
        }
        TCGEN05_FENCE_BEFORE();
        __syncthreads();
    }
    MBARRIER_WAIT_PARITY(sb + G_SM_MBAR, (NC - 1) & 1);
    TCGEN05_FENCE_AFTER();

    // epilogue: warps 0-3 -> accumulator 0 (rows 0-127),
    // warps 4-7 -> accumulator 1 at tmem+128 (rows 128-255); lanes (wid&3)*32
    {
        int half = wid >> 2, w4 = wid & 3;
        int m = bm + half * 128 + w4 * 32 + lid;
        uint32_t tb = tmem + half * 128;
        #pragma unroll
        for (int cb = 0; cb < 4; cb++) {
            uint32_t d[32];
            TCGEN05_LD_32X32B_X32(d, tb + cb * 32);
            TCGEN05_WAIT_LD();
            int n0 = bn + cb * 32;
            if (EPI == 1 || EPI == 3) {
                uint32_t hp[16], lp[16];
                #pragma unroll
                for (int j2 = 0; j2 < 16; j2++) {
                    float v0 = __uint_as_float(d[j2 * 2])     + __ldg(&bias[n0 + j2 * 2]);
                    float v1 = __uint_as_float(d[j2 * 2 + 1]) + __ldg(&bias[n0 + j2 * 2 + 1]);
                    if (EPI == 1) { v0 = fmaxf(v0, 0.f); v1 = fmaxf(v1, 0.f); }
                    float h0 = __bfloat162float(__float2bfloat16(v0));
                    float h1 = __bfloat162float(__float2bfloat16(v1));
                    hp[j2] = pack_bf16(h0, h1);
                    lp[j2] = pack_bf16(v0 - h0, v1 - h1);
                }
                #pragma unroll
                for (int q = 0; q < 2; q++) {
                    *(uint4*)(Chi + (size_t)m * N + n0 + q * 16)     = *(uint4*)&hp[q * 8];
                    *(uint4*)(Chi + (size_t)m * N + n0 + q * 16 + 8) = *(uint4*)&hp[q * 8 + 4];
                    *(uint4*)(Clo + (size_t)m * N + n0 + q * 16)     = *(uint4*)&lp[q * 8];
                    *(uint4*)(Clo + (size_t)m * N + n0 + q * 16 + 8) = *(uint4*)&lp[q * 8 + 4];
                }
            } else {
                #pragma unroll
                for (int j4 = 0; j4 < 8; j4++) {
                    float o[4];
                    #pragma unroll
                    for (int q = 0; q < 4; q++) {
                        int j = j4 * 4 + q;
                        float v = __uint_as_float(d[j]) + __ldg(&bias[n0 + j]);
                        if (EPI == 2) v = res[(size_t)m * N + n0 + j] + scl * v;
                        o[q] = v;
                    }
                    *(float4*)(C + (size_t)m * N + n0 + j4 * 4) = make_float4(o[0], o[1], o[2], o[3]);
                }
            }
        }
        TCGEN05_FENCE_BEFORE();
    }
    __syncthreads();
    if (tid == 0) MBARRIER_INVAL(sb + G_SM_MBAR);
    __syncthreads();
    if (wid == 0) TCGEN05_DEALLOC(tmem, 256);
#else
    // ======================= mma.sync fallback path (two 128-row halves) ====
    const int NCF = K / 64;
    for (int mh = 0; mh < 2; mh++) {
        const __nv_bfloat16* Ah2 = Ahb + (size_t)mh * 128 * K;
        const __nv_bfloat16* Al2 = Alb + (size_t)mh * 128 * K;
        int bm2 = bm + mh * 128;

        auto load_chunk = [&](int c) {
            const __nv_bfloat16* srcs[4] = {Ah2, Al2, Bhb, Blb};
            #pragma unroll
            for (int arr = 0; arr < 4; arr++) {
                const __nv_bfloat16* src = srcs[arr];
                char* tbp = smem + 1024 + arr * 16384;
                #pragma unroll
                for (int i = 0; i < 4; i++) {
                    int idx = i * 256 + tid;
                    int row = idx >> 3, v16 = idx & 7;
                    uint4 val = *(const uint4*)(src + (size_t)row * K + c * 64 + v16 * 8);
                    uint32_t off = SMEM_SWIZZLE_128B((uint32_t)(row * 128 + v16 * 16));
                    *(uint4*)(tbp + off) = val;
                }
            }
        };

        int wm = (wid & 3) * 32, wn = (wid >> 2) * 64;
        float acc[2][8][4];
        #pragma unroll
        for (int mi = 0; mi < 2; mi++)
            #pragma unroll
            for (int n = 0; n < 8; n++)
                #pragma unroll
                for (int q = 0; q < 4; q++) acc[mi][n][q] = 0.f;

        for (int c = 0; c < NCF; c++) {
            load_chunk(c);
            __syncthreads();
            uint32_t tAh = sb + 1024;
            uint32_t tAl = sb + 1024 + 16384;
            uint32_t tBh = sb + 1024 + 32768;
            uint32_t tBl = sb + 1024 + 49152;

            #pragma unroll
            for (int ks = 0; ks < 4; ks++) {
                int cb = ks * 32;
                int amat = lid >> 3;
                int arow = (lid & 7) + ((amat & 1) << 3);
                int abc  = cb + ((amat >> 1) << 4);
                uint32_t offA0 = SMEM_SWIZZLE_128B((uint32_t)((wm + arow) * 128 + abc));
                uint32_t offA1 = SMEM_SWIZZLE_128B((uint32_t)((wm + 16 + arow) * 128 + abc));
                uint32_t ah0[4], ah1[4], al0[4], al1[4];
                ldsm_x4(tAh + offA0, ah0);
                ldsm_x4(tAh + offA1, ah1);
                ldsm_x4(tAl + offA0, al0);
                ldsm_x4(tAl + offA1, al1);

                int bmat = (lid >> 3) & 1;
                int brow = lid & 7;
                int bbc  = cb + (bmat << 4);
                #pragma unroll
                for (int n = 0; n < 8; n++) {
                    uint32_t offB = SMEM_SWIZZLE_128B((uint32_t)((wn + n * 8 + brow) * 128 + bbc));
                    uint32_t bh[2], bl[2];
                    ldsm_x2(tBh + offB, bh);
                    ldsm_x2(tBl + offB, bl);
                    mma_16816(acc[0][n], ah0, bh);
                    mma_16816(acc[0][n], ah0, bl);
                    mma_16816(acc[0][n], al0, bh);
                    mma_16816(acc[1][n], ah1, bh);
                    mma_16816(acc[1][n], ah1, bl);
                    mma_16816(acc[1][n], al1, bh);
                }
            }
            __syncthreads();
        }

        #pragma unroll
        for (int mi = 0; mi < 2; mi++) {
            #pragma unroll
            for (int rr = 0; rr < 2; rr++) {
                int m = bm2 + wm + mi * 16 + (lid >> 2) + rr * 8;
                #pragma unroll
                for (int n = 0; n < 8; n++) {
                    int j0 = bn + wn + n * 8 + (lid & 3) * 2;
                    float v0 = acc[mi][n][rr * 2 + 0] + __ldg(&bias[j0]);
                    float v1 = acc[mi][n][rr * 2 + 1] + __ldg(&bias[j0 + 1]);
                    if (EPI == 1 || EPI == 3) {
                        if (EPI == 1) { v0 = fmaxf(v0, 0.f); v1 = fmaxf(v1, 0.f); }
                        __nv_bfloat16 h0 = __float2bfloat16(v0);
                        __nv_bfloat16 h1 = __float2bfloat16(v1);
                        Chi[(size_t)m * N + j0]     = h0;
                        Chi[(size_t)m * N + j0 + 1] = h1;
                        Clo[(size_t)m * N + j0]     = __float2bfloat16(v0 - __bfloat162float(h0));
                        Clo[(size_t)m * N + j0 + 1] = __float2bfloat16(v1 - __bfloat162float(h1));
                    } else {
                        if (EPI == 2) {
                            v0 = res[(size_t)m * N + j0]     + scl * v0;
                            v1 = res[(size_t)m * N + j0 + 1] + scl * v1;
                        }
                        *(float2*)(C + (size_t)m * N + j0) = make_float2(v0, v1);
                    }
                }
            }
        }
        __syncthreads();
    }
#endif
}

template<int EPI>
__global__ __launch_bounds__(256) void gemm_tc(
    const __nv_bfloat16* __restrict__ Ah, const __nv_bfloat16* __restrict__ Al,
    const __nv_bfloat16* __restrict__ Bh, const __nv_bfloat16* __restrict__ Bl,
    const float* __restrict__ bias, const float* __restrict__ res,
    const float* __restrict__ rs_ptr,
    float* __restrict__ C, __nv_bfloat16* __restrict__ Chi, __nv_bfloat16* __restrict__ Clo,
    int M, int N, int K)
{
    extern __shared__ char smem[];
    int bm = blockIdx.y * 256, bn = blockIdx.x * 128;
    gemm_body<EPI>(smem, smem_to_u32(smem), threadIdx.x,
        Ah + (size_t)bm * K, Al + (size_t)bm * K,
        Bh + (size_t)bn * K, Bl + (size_t)bn * K,
        bias, res, rs_ptr, C, Chi, Clo, bm, bn, N, K);
}

// merged QKV: grid.x = 24 (which = bx>>3), grid.y = 16 (256-row tiles)
__global__ __launch_bounds__(256) void gemm_qkv(
    const __nv_bfloat16* __restrict__ Ah, const __nv_bfloat16* __restrict__ Al,
    const __nv_bfloat16* __restrict__ wqh, const __nv_bfloat16* __restrict__ wql,
    const __nv_bfloat16* __restrict__ wkh, const __nv_bfloat16* __restrict__ wkl,
    const __nv_bfloat16* __restrict__ wvh, const __nv_bfloat16* __restrict__ wvl,
    const float* __restrict__ bq, const float* __restrict__ bk, const float* __restrict__ bv,
    __nv_bfloat16* __restrict__ qh, __nv_bfloat16* __restrict__ ql,
    __nv_bfloat16* __restrict__ kh, __nv_bfloat16* __restrict__ kl,
    __nv_bfloat16* __restrict__ vh, __nv_bfloat16* __restrict__ vl)
{
    extern __shared__ char smem[];
    int which = blockIdx.x >> 3;
    int bn = (blockIdx.x & 7) * 128, bm = blockIdx.y * 256;
    const __nv_bfloat16* Bh = (which == 0) ? wqh : (which == 1) ? wkh : wvh;
    const __nv_bfloat16* Bl = (which == 0) ? wql : (which == 1) ? wkl : wvl;
    const float* bias       = (which == 0) ? bq  : (which == 1) ? bk  : bv;
    __nv_bfloat16* Chi      = (which == 0) ? qh  : (which == 1) ? kh  : vh;
    __nv_bfloat16* Clo      = (which == 0) ? ql  : (which == 1) ? kl  : vl;
    gemm_body<3>(smem, smem_to_u32(smem), threadIdx.x,
        Ah + (size_t)bm * DM, Al + (size_t)bm * DM,
        Bh + (size_t)bn * DM, Bl + (size_t)bn * DM,
        bias, nullptr, nullptr, nullptr, Chi, Clo, bm, bn, DM, DM);
}

// ================ tensor-core causal relu-attention =========================
// v5: far-tile fast path (uniform rel-bias, no per-element mask/clip/LDS)
// + bf16x2 single-cvt repack. Bit-exact vs v3.
#define AT_SQH 0
#define AT_SQL 16384
#define AT_KV(s) (32768 + (s) * 32768)
#define AT_SRE 98304
#define AT_TOTAL (98304 + 1024)

__global__ __launch_bounds__(256) void attn_tc_kernel(
    const __nv_bfloat16* __restrict__ Qh, const __nv_bfloat16* __restrict__ Ql,
    const __nv_bfloat16* __restrict__ Kh, const __nv_bfloat16* __restrict__ Kl,
    const __nv_bfloat16* __restrict__ Vh, const __nv_bfloat16* __restrict__ Vl,
    const float* __restrict__ RE,
    __nv_bfloat16* __restrict__ Oh, __nv_bfloat16* __restrict__ Ol)
{
    extern __shared__ char sm[];
    uint32_t sb = smem_to_u32(sm);
    float* sre = (float*)(sm + AT_SRE);
    int tid = threadIdx.x, wid = tid >> 5, lid = tid & 31;
    int qt = (int)gridDim.x - 1 - (int)blockIdx.x;   // heavy tiles first
    int h = blockIdx.y, b = blockIdx.z;
    size_t base = ((size_t)b * TS) * DM + h * DH;
    int Q0 = qt * 128;

    if (tid < 255) sre[tid] = RE[tid * NH + h];

    auto loadKV_async = [&](int kt, int s) {
        uint32_t kb = sb + AT_KV(s);
        #pragma unroll
        for (int i = 0; i < 2; i++) {
            int idx = i * 256 + tid; int r = idx >> 3, c8 = idx & 7;
            size_t g = base + (size_t)(kt * 64 + r) * DM + c8 * 8;
            uint32_t off = SMEM_SWIZZLE_128B((uint32_t)(r * 128 + c8 * 16));
            CP_ASYNC16(kb + 0     + off, Kh + g);
            CP_ASYNC16(kb + 8192  + off, Kl + g);
            CP_ASYNC16(kb + 16384 + off, Vh + g);
            CP_ASYNC16(kb + 24576 + off, Vl + g);
        }
    };

    loadKV_async(0, 0); CP_COMMIT();

    #pragma unroll
    for (int i = 0; i < 4; i++) {
        int idx = i * 256 + tid; int r = idx >> 3, c8 = idx & 7;
        size_t g = base + (size_t)(Q0 + r) * DM + c8 * 8;
        uint32_t off = SMEM_SWIZZLE_128B((uint32_t)(r * 128 + c8 * 16));
        *(uint4*)(sm + AT_SQH + off) = *(const uint4*)(Qh + g);
        *(uint4*)(sm + AT_SQL + off) = *(const uint4*)(Ql + g);
    }
    CP_WAIT0();
    __syncthreads();

    uint32_t qa_h[4][4], qa_l[4][4];
    {
        int amat = lid >> 3;
        int arow = (lid & 7) + ((amat & 1) << 3);
        int acol = (amat >> 1) << 4;
        #pragma unroll
        for (int kk = 0; kk < 4; kk++) {
            uint32_t off = SMEM_SWIZZLE_128B((uint32_t)((wid * 16 + arow) * 128 + kk * 32 + acol));
            ldsm_x4(sb + AT_SQH + off, qa_h[kk]);
            ldsm_x4(sb + AT_SQL + off, qa_l[kk]);
        }
    }

    float acc[8][4];
    #pragma unroll
    for (int dn = 0; dn < 8; dn++)
        #pragma unroll
        for (int q = 0; q < 4; q++) acc[dn][q] = 0.f;
    float rs0 = 0.f, rs1 = 0.f;
    int g4 = lid >> 2, tg = lid & 3;
    int qrow0 = Q0 + wid * 16 + g4;
    int qmax  = Q0 + wid * 16 + 15;
    int wqbase = Q0 + wid * 16;

    int r1 = ((lid >> 4) & 1) * 8 + (lid & 7);
    int c1 = ((lid >> 3) & 1) << 4;
    int r2 = (((lid >> 3) & 1) << 3) + (lid & 7);
    int c2 = ((lid >> 4) & 1) << 4;

    const float c0 = sre[0];
    const int KT = 2 * qt + 2;
    for (int kt = 0; kt < KT; kt++) {
        int s = kt & 1;
        if (kt + 1 < KT) { loadKV_async(kt + 1, s ^ 1); CP_COMMIT(); }

        if (kt * 64 <= qmax) {
            uint32_t kvb = sb + AT_KV(s);
            bool far = (kt * 64 + 63 <= wqbase - 127);

            float sv_[8][4];
            #pragma unroll
            for (int np = 0; np < 4; np++) {
                sv_[2*np][0] = sv_[2*np][1] = sv_[2*np][2] = sv_[2*np][3] = 0.f;
                sv_[2*np+1][0] = sv_[2*np+1][1] = sv_[2*np+1][2] = sv_[2*np+1][3] = 0.f;
                #pragma unroll
                for (int kk = 0; kk < 4; kk++) {
                    uint32_t off = SMEM_SWIZZLE_128B(
                        (uint32_t)((np * 16 + r1) * 128 + kk * 32 + c1));
                    uint32_t rh[4], rl[4];
                    ldsm_x4(kvb + 0    + off, rh);
                    ldsm_x4(kvb + 8192 + off, rl);
                    mma_16816(sv_[2*np],   qa_h[kk], rh);
                    mma_16816(sv_[2*np],   qa_h[kk], rl);
                    mma_16816(sv_[2*np],   qa_l[kk], rh);
                    mma_16816(sv_[2*np+1], qa_h[kk], rh + 2);
                    mma_16816(sv_[2*np+1], qa_h[kk], rl + 2);
                    mma_16816(sv_[2*np+1], qa_l[kk], rh + 2);
                }
            }

            uint32_t wh[4][4], wl[4][4];
            #pragma unroll
            for (int n = 0; n < 8; n++) {
                float wv[4];
                if (far) {
                    #pragma unroll
                    for (int e = 0; e < 4; e++)
                        wv[e] = fmaxf(sv_[n][e] * 0.125f + c0, 0.f) + 1e-6f;
                } else {
                    int kc0 = kt * 64 + n * 8 + tg * 2;
                    #pragma unroll
                    for (int e = 0; e < 4; e++) {
                        int kg = kc0 + (e & 1);
                        int qg = qrow0 + ((e >> 1) << 3);
                        int rel = kg - qg;
                        int rc = (rel < -127 ? -127 : (rel > 127 ? 127 : rel)) + 127;
                        float sv = sv_[n][e] * 0.125f + sre[rc];
                        wv[e] = (kg <= qg) ? (fmaxf(sv, 0.f) + 1e-6f) : 0.f;
                    }
                }
                rs0 += wv[0] + wv[1];
                rs1 += wv[2] + wv[3];
                int kk = n >> 1, a0 = (n & 1) << 1;
                uint32_t hp01 = cvt_bf16x2(wv[0], wv[1]);
                uint32_t hp23 = cvt_bf16x2(wv[2], wv[3]);
                float h0 = __uint_as_float(hp01 << 16);
                float h1 = __uint_as_float(hp01 & 0xffff0000u);
                float h2 = __uint_as_float(hp23 << 16);
                float h3 = __uint_as_float(hp23 & 0xffff0000u);
                wh[kk][a0 + 0] = hp01;
                wh[kk][a0 + 1] = hp23;
                wl[kk][a0 + 0] = cvt_bf16x2(wv[0] - h0, wv[1] - h1);
                wl[kk][a0 + 1] = cvt_bf16x2(wv[2] - h2, wv[3] - h3);
            }

            #pragma unroll
            for (int kk = 0; kk < 4; kk++) {
                #pragma unroll
                for (int dp = 0; dp < 4; dp++) {
                    uint32_t off = SMEM_SWIZZLE_128B(
                        (uint32_t)((kk * 16 + r2) * 128 + dp * 32 + c2));
                    uint32_t vh4[4], vl4[4];
                    ldsm_x4_trans(kvb + 16384 + off, vh4);
                    ldsm_x4_trans(kvb + 24576 + off, vl4);
                    mma_16816(acc[2*dp],   wh[kk], vh4);
                    mma_16816(acc[2*dp],   wh[kk], vl4);
                    mma_16816(acc[2*dp],   wl[kk], vh4);
                    mma_16816(acc[2*dp+1], wh[kk], vh4 + 2);
                    mma_16816(acc[2*dp+1], wh[kk], vl4 + 2);
                    mma_16816(acc[2*dp+1], wl[kk], vh4 + 2);
                }
            }
        }
        CP_WAIT0();
        __syncthreads();
    }

    rs0 += __shfl_xor_sync(0xffffffffu, rs0, 1);
    rs0 += __shfl_xor_sync(0xffffffffu, rs0, 2);
    rs1 += __shfl_xor_sync(0xffffffffu, rs1, 1);
    rs1 += __shfl_xor_sync(0xffffffffu, rs1, 2);
    float inv0 = 1.f / (rs0 + 1e-6f);
    float inv1 = 1.f / (rs1 + 1e-6f);

    #pragma unroll
    for (int dn = 0; dn < 8; dn++) {
        float v0 = acc[dn][0] * inv0, v1 = acc[dn][1] * inv0;
        float v2 = acc[dn][2] * inv1, v3 = acc[dn][3] * inv1;
        size_t o0 = base + (size_t)qrow0 * DM + dn * 8 + tg * 2;
        size_t o1 = o0 + (size_t)8 * DM;
        uint32_t p01 = cvt_bf16x2(v0, v1);
        uint32_t p23 = cvt_bf16x2(v2, v3);
        float h0 = __uint_as_float(p01 << 16);
        float h1 = __uint_as_float(p01 & 0xffff0000u);
        float h2 = __uint_as_float(p23 << 16);
        float h3 = __uint_as_float(p23 & 0xffff0000u);
        *(uint32_t*)(Oh + o0) = p01;
        *(uint32_t*)(Oh + o1) = p23;
        *(uint32_t*)(Ol + o0) = cvt_bf16x2(v0 - h0, v1 - h1);
        *(uint32_t*)(Ol + o1) = cvt_bf16x2(v2 - h2, v3 - h3);
    }
}

// ---------------- driver ----------------------------------------------------
extern "C" void kernel_launch(void* const* d_in, const int* in_sizes, int n_in,
                              void* d_out, int out_size)
{
    const float* x   = (const float*)d_in[0];
    const float* Wq  = (const float*)d_in[2];
    const float* bq  = (const float*)d_in[3];
    const float* Wk  = (const float*)d_in[4];
    const float* bk  = (const float*)d_in[5];
    const float* Wv  = (const float*)d_in[6];
    const float* bv  = (const float*)d_in[7];
    const float* Wo  = (const float*)d_in[8];
    const float* bo  = (const float*)d_in[9];
    const float* re  = (const float*)d_in[10];
    const float* g1  = (const float*)d_in[11];
    const float* be1 = (const float*)d_in[12];
    const float* a1  = (const float*)d_in[13];
    const float* br1 = (const float*)d_in[14];
    const float* g2  = (const float*)d_in[15];
    const float* be2 = (const float*)d_in[16];
    const float* a2  = (const float*)d_in[17];
    const float* br2 = (const float*)d_in[18];
    const float* W1  = (const float*)d_in[19];
    const float* b1  = (const float*)d_in[20];
    const float* W2  = (const float*)d_in[21];
    const float* b2  = (const float*)d_in[22];
    const float* rs  = (const float*)d_in[23];
    float* out = (float*)d_out;

    float *px1;
    cudaGetSymbolAddress((void**)&px1,  g_x1);
    __nv_bfloat16 *lnh,*lnl,*qh,*ql,*kbh,*kbl,*vbh,*vbl,*ath,*atl,*hh,*hl,*fh,*fl;
    __nv_bfloat16 *wqh,*wql,*wkh,*wkl,*wvh,*wvl,*woh,*wol,*w1h,*w1l,*w2h,*w2l;
    cudaGetSymbolAddress((void**)&lnh, g_lnh); cudaGetSymbolAddress((void**)&lnl, g_lnl);
    cudaGetSymbolAddress((void**)&qh,  g_qh ); cudaGetSymbolAddress((void**)&ql,  g_ql );
    cudaGetSymbolAddress((void**)&kbh, g_kbh); cudaGetSymbolAddress((void**)&kbl, g_kbl);
    cudaGetSymbolAddress((void**)&vbh, g_vbh); cudaGetSymbolAddress((void**)&vbl, g_vbl);
    cudaGetSymbolAddress((void**)&ath, g_ath); cudaGetSymbolAddress((void**)&atl, g_atl);
    cudaGetSymbolAddress((void**)&hh,  g_hh ); cudaGetSymbolAddress((void**)&hl,  g_hl );
    cudaGetSymbolAddress((void**)&fh,  g_fh ); cudaGetSymbolAddress((void**)&fl,  g_fl );
    cudaGetSymbolAddress((void**)&wqh, g_wqh); cudaGetSymbolAddress((void**)&wql, g_wql);
    cudaGetSymbolAddress((void**)&wkh, g_wkh); cudaGetSymbolAddress((void**)&wkl, g_wkl);
    cudaGetSymbolAddress((void**)&wvh, g_wvh); cudaGetSymbolAddress((void**)&wvl, g_wvl);
    cudaGetSymbolAddress((void**)&woh, g_woh); cudaGetSymbolAddress((void**)&wol, g_wol);
    cudaGetSymbolAddress((void**)&w1h, g_w1h); cudaGetSymbolAddress((void**)&w1l, g_w1l);
    cudaGetSymbolAddress((void**)&w2h, g_w2h); cudaGetSymbolAddress((void**)&w2l, g_w2l);

    cudaFuncSetAttribute(gemm_tc<1>, cudaFuncAttributeMaxDynamicSharedMemorySize, G_SM_TOTAL);
    cudaFuncSetAttribute(gemm_tc<2>, cudaFuncAttributeMaxDynamicSharedMemorySize, G_SM_TOTAL);
    cudaFuncSetAttribute(gemm_qkv,   cudaFuncAttributeMaxDynamicSharedMemorySize, G_SM_TOTAL);
    cudaFuncSetAttribute(attn_tc_kernel, cudaFuncAttributeMaxDynamicSharedMemorySize, AT_TOTAL);

    // 0: all weight splits fused
    split6_kernel<<<dim3(1024, 6), 256>>>(
        Wq, Wk, Wv, Wo, W1, W2,
        wqh, wql, wkh, wkl, wvh, wvl, woh, wol, w1h, w1l, w2h, w2l);

    // 1: ln1 -> bf16 hi/lo
    ln_kernel<<<NT, 256>>>(x, g1, be1, a1, br1, lnh, lnl);

    // 2: merged QKV projections (256-row tiles) -> bf16 hi/lo
    gemm_qkv<<<dim3(24, NT / 256), 256, G_SM_TOTAL>>>(
        lnh, lnl, wqh, wql, wkh, wkl, wvh, wvl,
        bq, bk, bv, qh, ql, kbh, kbl, vbh, vbl);

    // 3: attention v5 -> bf16 hi/lo
    attn_tc_kernel<<<dim3(TS / 128, NH, NB), 256, AT_TOTAL>>>(
        qh, ql, kbh, kbl, vbh, vbl, re, ath, atl);

    // 4: O projection + residual
    gemm_tc<2><<<dim3(DM / 128, NT / 256), 256, G_SM_TOTAL>>>(
        ath, atl, woh, wol, bo, x, rs, px1, nullptr, nullptr, NT, DM, DM);

    // 5: ln2 -> bf16 hi/lo
    ln_kernel<<<NT, 256>>>(px1, g2, be2, a2, br2, hh, hl);

    // 6: FFN1 (relu) -> bf16 hi/lo
    gemm_tc<1><<<dim3(DF / 128, NT / 256), 256, G_SM_TOTAL>>>(
        hh, hl, w1h, w1l, b1, nullptr, nullptr, nullptr, fh, fl, NT, DF, DM);

    // 7: FFN2 + residual -> out
    gemm_tc<2><<<dim3(DM / 128, NT / 256), 256, G_SM_TOTAL>>>(
        fh, fl, w2h, w2l, b2, px1, rs, out, nullptr, nullptr, NT, DM, DF);
}